// round 13
// baseline (speedup 1.0000x reference)
#include <cuda_runtime.h>
#include <math.h>

#define NROI 116
#define NGR  128
#define HID  64
#define EDIM 5
#define INCH 116
#define EMBD 16
#define CIN  (INCH + EMBD)
#define EPG  (NROI * NROI)
#define NNODE (NROI * NGR)
#define RS   68
#define THR  928
#define GTHR 512
#define CH   4
#define NC   29
#define ESFC  (CH * NROI * EDIM)   /* 2320 floats per buffer */
#define ESFC4 (ESFC / 4)           /* 580 float4 */

typedef unsigned long long u64;

__device__ float g_hpre[NNODE * HID];
__device__ float g_hA[NNODE * HID];
__device__ float g_hB[NNODE * HID];
__device__ float g_sum[HID];
__device__ float g_sumsq[HID];
__device__ float g_scale[HID];
__device__ float g_shift[HID];
__device__ float g_t[NNODE];
__device__ float g_MS[2];

__device__ __forceinline__ float4 ld4(const float* p) { return *reinterpret_cast<const float4*>(p); }
__device__ __forceinline__ void st4(float* p, float4 v) { *reinterpret_cast<float4*>(p) = v; }
__device__ __forceinline__ float4 fma4(float a, float4 b, float4 c) {
    c.x = fmaf(a, b.x, c.x); c.y = fmaf(a, b.y, c.y);
    c.z = fmaf(a, b.z, c.z); c.w = fmaf(a, b.w, c.w); return c;
}
__device__ __forceinline__ float4 add4(float4 a, float4 b) {
    a.x += b.x; a.y += b.y; a.z += b.z; a.w += b.w; return a;
}
__device__ __forceinline__ float4 relu4(float4 a) {
    a.x = fmaxf(a.x, 0.f); a.y = fmaxf(a.y, 0.f);
    a.z = fmaxf(a.z, 0.f); a.w = fmaxf(a.w, 0.f); return a;
}
__device__ __forceinline__ float4 scale4(float4 a, float f) {
    a.x *= f; a.y *= f; a.z *= f; a.w *= f; return a;
}
__device__ __forceinline__ float4 zero4() { return make_float4(0.f, 0.f, 0.f, 0.f); }

__device__ __forceinline__ u64 pk2(float x, float y) {
    u64 r; asm("mov.b64 %0,{%1,%2};" : "=l"(r) : "f"(x), "f"(y)); return r;
}
__device__ __forceinline__ u64 bc2(float x) { return pk2(x, x); }
__device__ __forceinline__ void up2(u64 v, float& x, float& y) {
    asm("mov.b64 {%0,%1},%2;" : "=f"(x), "=f"(y) : "l"(v));
}
__device__ __forceinline__ u64 f2fma(u64 a, u64 b, u64 c) {
    u64 r; asm("fma.rn.f32x2 %0,%1,%2,%3;" : "=l"(r) : "l"(a), "l"(b), "l"(c)); return r;
}
__device__ __forceinline__ void ld4p(const float* p, u64& a, u64& b) {
    float4 v = ld4(p); a = pk2(v.x, v.y); b = pk2(v.z, v.w);
}

__device__ __forceinline__ void cpa16(void* smem_dst, const void* gsrc) {
    unsigned s = (unsigned)__cvta_generic_to_shared(smem_dst);
    asm volatile("cp.async.cg.shared.global [%0], [%1], 16;" :: "r"(s), "l"(gsrc) : "memory");
}
#define CPA_COMMIT()  asm volatile("cp.async.commit_group;" ::: "memory")
#define CPA_WAIT0()   asm volatile("cp.async.wait_group 0;" ::: "memory")
#define CPA_WAIT1()   asm volatile("cp.async.wait_group 1;" ::: "memory")

__global__ void k_init() {
    int t = threadIdx.x;
    if (t < HID) { g_sum[t] = 0.f; g_sumsq[t] = 0.f; }
}

__global__ void __launch_bounds__(THR) k_encode(
    const float* __restrict__ x, const float* __restrict__ emb,
    const int* __restrict__ gid,
    const float* __restrict__ W, const float* __restrict__ b)
{
    extern __shared__ float sm[];
    float* XC = sm;
    float* WE = XC + NROI * CIN;
    float* HS = WE + CIN * HID;
    float* BS = HS + NROI * RS;
    int g = blockIdx.x, tid = threadIdx.x;

    for (int i = tid; i < CIN * HID; i += THR) WE[i] = W[i];
    if (tid < HID) BS[tid] = b[tid];
    const float* xg = x + (size_t)g * NROI * INCH;
    for (int i = tid; i < NROI * INCH; i += THR) {
        int n = i / INCH, c = i - n * INCH;
        XC[n * CIN + c] = xg[i];
    }
    for (int i = tid; i < NROI * EMBD; i += THR) {
        int n = i / EMBD, k = i - n * EMBD;
        XC[n * CIN + INCH + k] = emb[gid[g * NROI + n] * EMBD + k];
    }
    __syncthreads();

    int n = tid >> 3, jg = tid & 7, j0 = jg * 8;
    {
        float4 a0 = ld4(BS + j0), a1 = ld4(BS + j0 + 4);
        const float* xr = XC + n * CIN;
        #pragma unroll 4
        for (int c = 0; c < CIN; c++) {
            float xv = xr[c];
            const float* wr = WE + c * HID + j0;
            a0 = fma4(xv, ld4(wr), a0);
            a1 = fma4(xv, ld4(wr + 4), a1);
        }
        a0 = relu4(a0); a1 = relu4(a1);
        float* hp = g_hpre + ((size_t)g * NROI + n) * HID + j0;
        float* hs = HS + n * RS + j0;
        st4(hp, a0); st4(hp + 4, a1);
        st4(hs, a0); st4(hs + 4, a1);
    }
    __syncthreads();

    if (tid < HID) {
        float s1 = 0.f, s2 = 0.f;
        for (int r = 0; r < NROI; r++) {
            float v = HS[r * RS + tid];
            s1 += v; s2 += v * v;
        }
        atomicAdd(&g_sum[tid], s1);
        atomicAdd(&g_sumsq[tid], s2);
    }
}

__global__ void k_bnfin(const float* __restrict__ gg, const float* __restrict__ gb) {
    int j = threadIdx.x;
    if (j < HID) {
        const float invN = 1.0f / (float)NNODE;
        float mu  = g_sum[j] * invN;
        float var = g_sumsq[j] * invN - mu * mu;
        float sc  = gg[j] * rsqrtf(var + 1e-5f);
        g_scale[j] = sc;
        g_shift[j] = gb[j] - mu * sc;
    }
}

// ---------------- GINE: 512 thr, 2 dst/thread, double-buffered staging -----
__global__ void __launch_bounds__(GTHR) k_gine(
    const float* __restrict__ ea,
    const float* __restrict__ We, const float* __restrict__ be,
    const float* __restrict__ W1, const float* __restrict__ b1,
    const float* __restrict__ W2, const float* __restrict__ b2)
{
    extern __shared__ float sm[];
    float* H   = sm;                    // NROI*RS : BN(h) + be
    float* AG  = H + NROI * RS;
    float* W1s = AG + NROI * RS;
    float* W2s = W1s + HID * HID;
    float* WEs = W2s + HID * HID;
    float* ES  = WEs + EDIM * HID;      // 2 * ESFC
    float* BEs = ES + 2 * ESFC;
    float* B1s = BEs + HID;
    float* B2s = B1s + HID;
    int g = blockIdx.x, tid = threadIdx.x;

    for (int i = tid; i < HID * HID; i += GTHR) { W1s[i] = W1[i]; W2s[i] = W2[i]; }
    if (tid < EDIM * HID) WEs[tid] = We[tid];
    if (tid < HID) { BEs[tid] = be[tid]; B1s[tid] = b1[tid]; B2s[tid] = b2[tid]; }
    const float* hp = g_hpre + (size_t)g * NROI * HID;
    for (int i = tid; i < NROI * HID; i += GTHR) {
        int n = i >> 6, j = i & 63;
        H[n * RS + j] = hp[i] * g_scale[j] + g_shift[j] + __ldg(be + j);
    }

    int dl = tid >> 3, jg = tid & 7, j0 = jg * 8;
    int d0 = (dl < 58) ? dl : 57;
    int d1 = d0 + 58;

    const float4* eaq = reinterpret_cast<const float4*>(ea + (size_t)g * EPG * EDIM);
    float4* buf0 = reinterpret_cast<float4*>(ES);
    float4* buf1 = buf0 + ESFC4;
    // prologue: stage chunk 0
    for (int i = tid; i < ESFC4; i += GTHR) cpa16(buf0 + i, eaq + i);
    CPA_COMMIT();
    __syncthreads();   // also covers H/weights init

    u64 W00, W01, W02, W03, W10, W11, W12, W13, W20, W21, W22, W23,
        W30, W31, W32, W33, W40, W41, W42, W43;
    ld4p(WEs + 0 * HID + j0, W00, W01); ld4p(WEs + 0 * HID + j0 + 4, W02, W03);
    ld4p(WEs + 1 * HID + j0, W10, W11); ld4p(WEs + 1 * HID + j0 + 4, W12, W13);
    ld4p(WEs + 2 * HID + j0, W20, W21); ld4p(WEs + 2 * HID + j0 + 4, W22, W23);
    ld4p(WEs + 3 * HID + j0, W30, W31); ld4p(WEs + 3 * HID + j0 + 4, W32, W33);
    ld4p(WEs + 4 * HID + j0, W40, W41); ld4p(WEs + 4 * HID + j0 + 4, W42, W43);

    float4 accA0 = zero4(), accA1 = zero4(), accB0 = zero4(), accB1 = zero4();

    for (int c = 0; c < NC; c++) {
        float4* cur = (c & 1) ? buf1 : buf0;
        float4* nxt = (c & 1) ? buf0 : buf1;
        if (c + 1 < NC) {
            const float4* src = eaq + (c + 1) * ESFC4;
            for (int i = tid; i < ESFC4; i += GTHR) cpa16(nxt + i, src + i);
            CPA_COMMIT();
            CPA_WAIT1();
        } else {
            CPA_WAIT0();
        }
        __syncthreads();

        const float* ESc = reinterpret_cast<const float*>(cur);
        const float* hrb = H + j0 + (c * CH) * RS;
        #pragma unroll
        for (int sl = 0; sl < CH; sl++) {
            const float* eA = ESc + sl * (NROI * EDIM) + d0 * EDIM;
            const float* eB = ESc + sl * (NROI * EDIM) + d1 * EDIM;
            float a0 = eA[0], a1 = eA[1], a2 = eA[2], a3 = eA[3], a4 = eA[4];
            float b0 = eB[0], b1 = eB[1], b2 = eB[2], b3 = eB[3], b4 = eB[4];
            const float* hr = hrb + sl * RS;
            float4 h0 = ld4(hr), h1 = ld4(hr + 4);

            u64 E0 = bc2(a0), E1 = bc2(a1), E2 = bc2(a2), E3 = bc2(a3), E4 = bc2(a4);
            u64 pA0 = f2fma(E0, W00, 0ull), pA1 = f2fma(E0, W01, 0ull);
            u64 pA2 = f2fma(E0, W02, 0ull), pA3 = f2fma(E0, W03, 0ull);
            pA0 = f2fma(E1, W10, pA0); pA1 = f2fma(E1, W11, pA1);
            pA2 = f2fma(E1, W12, pA2); pA3 = f2fma(E1, W13, pA3);
            pA0 = f2fma(E2, W20, pA0); pA1 = f2fma(E2, W21, pA1);
            pA2 = f2fma(E2, W22, pA2); pA3 = f2fma(E2, W23, pA3);
            pA0 = f2fma(E3, W30, pA0); pA1 = f2fma(E3, W31, pA1);
            pA2 = f2fma(E3, W32, pA2); pA3 = f2fma(E3, W33, pA3);
            pA0 = f2fma(E4, W40, pA0); pA1 = f2fma(E4, W41, pA1);
            pA2 = f2fma(E4, W42, pA2); pA3 = f2fma(E4, W43, pA3);

            u64 F0 = bc2(b0), F1 = bc2(b1), F2 = bc2(b2), F3 = bc2(b3), F4 = bc2(b4);
            u64 pB0 = f2fma(F0, W00, 0ull), pB1 = f2fma(F0, W01, 0ull);
            u64 pB2 = f2fma(F0, W02, 0ull), pB3 = f2fma(F0, W03, 0ull);
            pB0 = f2fma(F1, W10, pB0); pB1 = f2fma(F1, W11, pB1);
            pB2 = f2fma(F1, W12, pB2); pB3 = f2fma(F1, W13, pB3);
            pB0 = f2fma(F2, W20, pB0); pB1 = f2fma(F2, W21, pB1);
            pB2 = f2fma(F2, W22, pB2); pB3 = f2fma(F2, W23, pB3);
            pB0 = f2fma(F3, W30, pB0); pB1 = f2fma(F3, W31, pB1);
            pB2 = f2fma(F3, W32, pB2); pB3 = f2fma(F3, W33, pB3);
            pB0 = f2fma(F4, W40, pB0); pB1 = f2fma(F4, W41, pB1);
            pB2 = f2fma(F4, W42, pB2); pB3 = f2fma(F4, W43, pB3);

            float q0, q1, q2, q3, q4, q5, q6, q7;
            up2(pA0, q0, q1); up2(pA1, q2, q3); up2(pA2, q4, q5); up2(pA3, q6, q7);
            accA0.x += fmaxf(h0.x + q0, 0.f); accA0.y += fmaxf(h0.y + q1, 0.f);
            accA0.z += fmaxf(h0.z + q2, 0.f); accA0.w += fmaxf(h0.w + q3, 0.f);
            accA1.x += fmaxf(h1.x + q4, 0.f); accA1.y += fmaxf(h1.y + q5, 0.f);
            accA1.z += fmaxf(h1.z + q6, 0.f); accA1.w += fmaxf(h1.w + q7, 0.f);
            up2(pB0, q0, q1); up2(pB1, q2, q3); up2(pB2, q4, q5); up2(pB3, q6, q7);
            accB0.x += fmaxf(h0.x + q0, 0.f); accB0.y += fmaxf(h0.y + q1, 0.f);
            accB0.z += fmaxf(h0.z + q2, 0.f); accB0.w += fmaxf(h0.w + q3, 0.f);
            accB1.x += fmaxf(h1.x + q4, 0.f); accB1.y += fmaxf(h1.y + q5, 0.f);
            accB1.z += fmaxf(h1.z + q6, 0.f); accB1.w += fmaxf(h1.w + q7, 0.f);
        }
        __syncthreads();
    }

    if (dl < 58) {
        float4 be0 = ld4(BEs + j0), be1 = ld4(BEs + j0 + 4);
        const float* hdA = H + d0 * RS + j0;
        const float* hdB = H + d1 * RS + j0;
        float* agA = AG + d0 * RS + j0;
        float* agB = AG + d1 * RS + j0;
        float4 t;
        t = ld4(hdA);     st4(agA,     add4(accA0, make_float4(t.x - be0.x, t.y - be0.y, t.z - be0.z, t.w - be0.w)));
        t = ld4(hdA + 4); st4(agA + 4, add4(accA1, make_float4(t.x - be1.x, t.y - be1.y, t.z - be1.z, t.w - be1.w)));
        t = ld4(hdB);     st4(agB,     add4(accB0, make_float4(t.x - be0.x, t.y - be0.y, t.z - be0.z, t.w - be0.w)));
        t = ld4(hdB + 4); st4(agB + 4, add4(accB1, make_float4(t.x - be1.x, t.y - be1.y, t.z - be1.z, t.w - be1.w)));
    }
    __syncthreads();

    // MLP layer 1
    #pragma unroll 1
    for (int batch = 0; batch < 2; batch++) {
        int n = (tid >> 3) + batch * 64;
        if (n < NROI) {
            float4 a0 = ld4(B1s + j0), a1 = ld4(B1s + j0 + 4);
            const float* inr = AG + n * RS;
            #pragma unroll 4
            for (int c = 0; c < HID; c++) {
                float xv = inr[c];
                const float* wr = W1s + c * HID + j0;
                a0 = fma4(xv, ld4(wr), a0);
                a1 = fma4(xv, ld4(wr + 4), a1);
            }
            float* hr2 = H + n * RS + j0;
            st4(hr2, relu4(a0)); st4(hr2 + 4, relu4(a1));
        }
    }
    __syncthreads();

    // MLP layer 2 -> relu -> g_hA
    #pragma unroll 1
    for (int batch = 0; batch < 2; batch++) {
        int n = (tid >> 3) + batch * 64;
        if (n < NROI) {
            float4 a0 = ld4(B2s + j0), a1 = ld4(B2s + j0 + 4);
            const float* inr = H + n * RS;
            #pragma unroll 4
            for (int c = 0; c < HID; c++) {
                float xv = inr[c];
                const float* wr = W2s + c * HID + j0;
                a0 = fma4(xv, ld4(wr), a0);
                a1 = fma4(xv, ld4(wr + 4), a1);
            }
            float* og = g_hA + ((size_t)g * NROI + n) * HID + j0;
            st4(og, relu4(a0)); st4(og + 4, relu4(a1));
        }
    }
}

// ------- GATv2: 512 thr, 2 dst/thread, double-buffered, lazy-rescale -------
__global__ void __launch_bounds__(GTHR) k_gat(
    int layer, const float* __restrict__ ea,
    const float* __restrict__ Wl_all, const float* __restrict__ bl_all,
    const float* __restrict__ Wr_all, const float* __restrict__ br_all,
    const float* __restrict__ att_all, const float* __restrict__ We_all,
    const float* __restrict__ bias_all)
{
    const float* in  = (layer == 0) ? g_hA : g_hB;
    float*       op  = (layer == 0) ? g_hB : g_hA;
    const float* Wl  = Wl_all  + layer * HID * HID;
    const float* bl  = bl_all  + layer * HID;
    const float* Wr  = Wr_all  + layer * HID * HID;
    const float* br  = br_all  + layer * HID;
    const float* att = att_all + layer * HID;
    const float* Wee = We_all  + layer * EDIM * HID;
    const float* bia = bias_all + layer * HID;

    extern __shared__ float sm[];
    float* H   = sm;
    float* XL  = H + NROI * RS;
    float* XR  = XL + NROI * RS;
    float* Ws  = XR + NROI * RS;
    float* WEs = Ws + HID * HID;
    float* ES  = WEs + EDIM * HID;      // 2 * ESFC
    float* ATT = ES + 2 * ESFC;
    float* BV  = ATT + HID;
    float* BI  = BV + HID;
    int g = blockIdx.x, tid = threadIdx.x;

    const float* ing = in + (size_t)g * NROI * HID;
    for (int i = tid; i < NROI * HID; i += GTHR)
        H[(i >> 6) * RS + (i & 63)] = ing[i];
    for (int i = tid; i < HID * HID; i += GTHR) Ws[i] = Wl[i];
    if (tid < EDIM * HID) WEs[tid] = Wee[tid];
    if (tid < HID) { ATT[tid] = att[tid]; BV[tid] = bl[tid]; BI[tid] = bia[tid]; }
    __syncthreads();

    int nb = tid >> 3, jg = tid & 7, j0 = jg * 8;

    #pragma unroll 1
    for (int batch = 0; batch < 2; batch++) {
        int n = nb + batch * 64;
        if (n < NROI) {
            float4 a0 = ld4(BV + j0), a1 = ld4(BV + j0 + 4);
            const float* hr = H + n * RS;
            #pragma unroll 4
            for (int c = 0; c < HID; c++) {
                float xv = hr[c];
                const float* wr = Ws + c * HID + j0;
                a0 = fma4(xv, ld4(wr), a0);
                a1 = fma4(xv, ld4(wr + 4), a1);
            }
            float* o = XL + n * RS + j0;
            st4(o, a0); st4(o + 4, a1);
        }
    }
    __syncthreads();
    for (int i = tid; i < HID * HID; i += GTHR) Ws[i] = Wr[i];
    if (tid < HID) BV[tid] = br[tid];
    __syncthreads();
    #pragma unroll 1
    for (int batch = 0; batch < 2; batch++) {
        int n = nb + batch * 64;
        if (n < NROI) {
            float4 a0 = ld4(BV + j0), a1 = ld4(BV + j0 + 4);
            const float* hr = H + n * RS;
            #pragma unroll 4
            for (int c = 0; c < HID; c++) {
                float xv = hr[c];
                const float* wr = Ws + c * HID + j0;
                a0 = fma4(xv, ld4(wr), a0);
                a1 = fma4(xv, ld4(wr + 4), a1);
            }
            float* o = XR + n * RS + j0;
            st4(o, a0); st4(o + 4, a1);
        }
    }

    int dl = tid >> 3;
    int d0 = (dl < 58) ? dl : 57;
    int d1 = d0 + 58;

    const float4* eaq = reinterpret_cast<const float4*>(ea + (size_t)g * EPG * EDIM);
    float4* buf0 = reinterpret_cast<float4*>(ES);
    float4* buf1 = buf0 + ESFC4;
    for (int i = tid; i < ESFC4; i += GTHR) cpa16(buf0 + i, eaq + i);
    CPA_COMMIT();
    __syncthreads();   // covers XR writes too

    u64 W00, W01, W02, W03, W10, W11, W12, W13, W20, W21, W22, W23,
        W30, W31, W32, W33, W40, W41, W42, W43;
    ld4p(WEs + 0 * HID + j0, W00, W01); ld4p(WEs + 0 * HID + j0 + 4, W02, W03);
    ld4p(WEs + 1 * HID + j0, W10, W11); ld4p(WEs + 1 * HID + j0 + 4, W12, W13);
    ld4p(WEs + 2 * HID + j0, W20, W21); ld4p(WEs + 2 * HID + j0 + 4, W22, W23);
    ld4p(WEs + 3 * HID + j0, W30, W31); ld4p(WEs + 3 * HID + j0 + 4, W32, W33);
    ld4p(WEs + 4 * HID + j0, W40, W41); ld4p(WEs + 4 * HID + j0 + 4, W42, W43);

    float4 at0 = ld4(ATT + j0), at1 = ld4(ATT + j0 + 4);
    float4 xa0 = ld4(XR + d0 * RS + j0), xa1 = ld4(XR + d0 * RS + j0 + 4);
    float4 xb0 = ld4(XR + d1 * RS + j0), xb1 = ld4(XR + d1 * RS + j0 + 4);
    float4 accA0 = zero4(), accA1 = zero4(), accB0 = zero4(), accB1 = zero4();
    float mA = -3.0e38f, swA = 0.f, mB = -3.0e38f, swB = 0.f;

    for (int c = 0; c < NC; c++) {
        float4* cur = (c & 1) ? buf1 : buf0;
        float4* nxt = (c & 1) ? buf0 : buf1;
        if (c + 1 < NC) {
            const float4* src = eaq + (c + 1) * ESFC4;
            for (int i = tid; i < ESFC4; i += GTHR) cpa16(nxt + i, src + i);
            CPA_COMMIT();
            CPA_WAIT1();
        } else {
            CPA_WAIT0();
        }
        __syncthreads();

        const float* ESc = reinterpret_cast<const float*>(cur);
        const float* xlb = XL + j0 + (c * CH) * RS;
        #pragma unroll
        for (int sl = 0; sl < CH; sl++) {
            const float* eA = ESc + sl * (NROI * EDIM) + d0 * EDIM;
            const float* eB = ESc + sl * (NROI * EDIM) + d1 * EDIM;
            float a0 = eA[0], a1 = eA[1], a2 = eA[2], a3 = eA[3], a4 = eA[4];
            float b0 = eB[0], b1 = eB[1], b2 = eB[2], b3 = eB[3], b4 = eB[4];
            const float* xlp = xlb + sl * RS;
            float4 xl0 = ld4(xlp), xl1 = ld4(xlp + 4);

            u64 E0 = bc2(a0), E1 = bc2(a1), E2 = bc2(a2), E3 = bc2(a3), E4 = bc2(a4);
            u64 pA0 = f2fma(E0, W00, 0ull), pA1 = f2fma(E0, W01, 0ull);
            u64 pA2 = f2fma(E0, W02, 0ull), pA3 = f2fma(E0, W03, 0ull);
            pA0 = f2fma(E1, W10, pA0); pA1 = f2fma(E1, W11, pA1);
            pA2 = f2fma(E1, W12, pA2); pA3 = f2fma(E1, W13, pA3);
            pA0 = f2fma(E2, W20, pA0); pA1 = f2fma(E2, W21, pA1);
            pA2 = f2fma(E2, W22, pA2); pA3 = f2fma(E2, W23, pA3);
            pA0 = f2fma(E3, W30, pA0); pA1 = f2fma(E3, W31, pA1);
            pA2 = f2fma(E3, W32, pA2); pA3 = f2fma(E3, W33, pA3);
            pA0 = f2fma(E4, W40, pA0); pA1 = f2fma(E4, W41, pA1);
            pA2 = f2fma(E4, W42, pA2); pA3 = f2fma(E4, W43, pA3);

            u64 F0 = bc2(b0), F1 = bc2(b1), F2 = bc2(b2), F3 = bc2(b3), F4 = bc2(b4);
            u64 pB0 = f2fma(F0, W00, 0ull), pB1 = f2fma(F0, W01, 0ull);
            u64 pB2 = f2fma(F0, W02, 0ull), pB3 = f2fma(F0, W03, 0ull);
            pB0 = f2fma(F1, W10, pB0); pB1 = f2fma(F1, W11, pB1);
            pB2 = f2fma(F1, W12, pB2); pB3 = f2fma(F1, W13, pB3);
            pB0 = f2fma(F2, W20, pB0); pB1 = f2fma(F2, W21, pB1);
            pB2 = f2fma(F2, W22, pB2); pB3 = f2fma(F2, W23, pB3);
            pB0 = f2fma(F3, W30, pB0); pB1 = f2fma(F3, W31, pB1);
            pB2 = f2fma(F3, W32, pB2); pB3 = f2fma(F3, W33, pB3);
            pB0 = f2fma(F4, W40, pB0); pB1 = f2fma(F4, W41, pB1);
            pB2 = f2fma(F4, W42, pB2); pB3 = f2fma(F4, W43, pB3);

            float q0, q1, q2, q3, q4, q5, q6, q7;
            float u, pA = 0.f, pB = 0.f;
            up2(pA0, q0, q1); up2(pA1, q2, q3); up2(pA2, q4, q5); up2(pA3, q6, q7);
            u = xl0.x + xa0.x + q0; pA = fmaf(at0.x, fmaxf(u, 0.f) + 0.2f * fminf(u, 0.f), pA);
            u = xl0.y + xa0.y + q1; pA = fmaf(at0.y, fmaxf(u, 0.f) + 0.2f * fminf(u, 0.f), pA);
            u = xl0.z + xa0.z + q2; pA = fmaf(at0.z, fmaxf(u, 0.f) + 0.2f * fminf(u, 0.f), pA);
            u = xl0.w + xa0.w + q3; pA = fmaf(at0.w, fmaxf(u, 0.f) + 0.2f * fminf(u, 0.f), pA);
            u = xl1.x + xa1.x + q4; pA = fmaf(at1.x, fmaxf(u, 0.f) + 0.2f * fminf(u, 0.f), pA);
            u = xl1.y + xa1.y + q5; pA = fmaf(at1.y, fmaxf(u, 0.f) + 0.2f * fminf(u, 0.f), pA);
            u = xl1.z + xa1.z + q6; pA = fmaf(at1.z, fmaxf(u, 0.f) + 0.2f * fminf(u, 0.f), pA);
            u = xl1.w + xa1.w + q7; pA = fmaf(at1.w, fmaxf(u, 0.f) + 0.2f * fminf(u, 0.f), pA);
            up2(pB0, q0, q1); up2(pB1, q2, q3); up2(pB2, q4, q5); up2(pB3, q6, q7);
            u = xl0.x + xb0.x + q0; pB = fmaf(at0.x, fmaxf(u, 0.f) + 0.2f * fminf(u, 0.f), pB);
            u = xl0.y + xb0.y + q1; pB = fmaf(at0.y, fmaxf(u, 0.f) + 0.2f * fminf(u, 0.f), pB);
            u = xl0.z + xb0.z + q2; pB = fmaf(at0.z, fmaxf(u, 0.f) + 0.2f * fminf(u, 0.f), pB);
            u = xl0.w + xb0.w + q3; pB = fmaf(at0.w, fmaxf(u, 0.f) + 0.2f * fminf(u, 0.f), pB);
            u = xl1.x + xb1.x + q4; pB = fmaf(at1.x, fmaxf(u, 0.f) + 0.2f * fminf(u, 0.f), pB);
            u = xl1.y + xb1.y + q5; pB = fmaf(at1.y, fmaxf(u, 0.f) + 0.2f * fminf(u, 0.f), pB);
            u = xl1.z + xb1.z + q6; pB = fmaf(at1.z, fmaxf(u, 0.f) + 0.2f * fminf(u, 0.f), pB);
            u = xl1.w + xb1.w + q7; pB = fmaf(at1.w, fmaxf(u, 0.f) + 0.2f * fminf(u, 0.f), pB);

            pA += __shfl_xor_sync(0xffffffffu, pA, 1);
            pB += __shfl_xor_sync(0xffffffffu, pB, 1);
            pA += __shfl_xor_sync(0xffffffffu, pA, 2);
            pB += __shfl_xor_sync(0xffffffffu, pB, 2);
            pA += __shfl_xor_sync(0xffffffffu, pA, 4);
            pB += __shfl_xor_sync(0xffffffffu, pB, 4);

            float wA;
            if (pA <= mA) {
                wA = __expf(pA - mA);
            } else {
                float fac = __expf(mA - pA);
                swA *= fac;
                accA0 = scale4(accA0, fac); accA1 = scale4(accA1, fac);
                mA = pA;
                wA = 1.f;
            }
            swA += wA;
            accA0 = fma4(wA, xl0, accA0);
            accA1 = fma4(wA, xl1, accA1);

            float wB;
            if (pB <= mB) {
                wB = __expf(pB - mB);
            } else {
                float fac = __expf(mB - pB);
                swB *= fac;
                accB0 = scale4(accB0, fac); accB1 = scale4(accB1, fac);
                mB = pB;
                wB = 1.f;
            }
            swB += wB;
            accB0 = fma4(wB, xl0, accB0);
            accB1 = fma4(wB, xl1, accB1);
        }
        __syncthreads();
    }

    if (dl < 58) {
        float4 bi0 = ld4(BI + j0), bi1 = ld4(BI + j0 + 4);
        float invA = 1.f / (swA + 1e-16f);
        float invB = 1.f / (swB + 1e-16f);
        float* ogA = op + ((size_t)g * NROI + d0) * HID + j0;
        float* ogB = op + ((size_t)g * NROI + d1) * HID + j0;
        st4(ogA,     relu4(add4(scale4(accA0, invA), bi0)));
        st4(ogA + 4, relu4(add4(scale4(accA1, invA), bi1)));
        st4(ogB,     relu4(add4(scale4(accB0, invB), bi0)));
        st4(ogB + 4, relu4(add4(scale4(accB1, invB), bi1)));
    }
}

__global__ void __launch_bounds__(512) k_pool1(
    const float* __restrict__ W, const float* __restrict__ b,
    const float* __restrict__ w2)
{
    __shared__ __align__(16) float H[NROI * RS];
    __shared__ __align__(16) float Ws[HID * HID];
    __shared__ __align__(16) float Bs[HID];
    __shared__ __align__(16) float W2s[HID];
    int g = blockIdx.x, tid = threadIdx.x;
    const float* ing = g_hA + (size_t)g * NROI * HID;
    for (int i = tid; i < NROI * HID; i += 512)
        H[(i >> 6) * RS + (i & 63)] = ing[i];
    for (int i = tid; i < HID * HID; i += 512) Ws[i] = W[i];
    if (tid < HID) { Bs[tid] = b[tid]; W2s[tid] = w2[tid]; }
    __syncthreads();

    int nn = tid >> 2, jg = tid & 3, j0 = jg * 16;
    bool valid = (tid < 464);
    int n = valid ? nn : 0;

    float4 a[4];
    #pragma unroll
    for (int q = 0; q < 4; q++) a[q] = ld4(Bs + j0 + 4 * q);
    const float* hr = H + n * RS;
    #pragma unroll 4
    for (int c = 0; c < HID; c++) {
        float xv = hr[c];
        const float* wr = Ws + c * HID + j0;
        a[0] = fma4(xv, ld4(wr), a[0]);
        a[1] = fma4(xv, ld4(wr + 4), a[1]);
        a[2] = fma4(xv, ld4(wr + 8), a[2]);
        a[3] = fma4(xv, ld4(wr + 12), a[3]);
    }
    float part = 0.f;
    #pragma unroll
    for (int q = 0; q < 4; q++) {
        float4 w4 = ld4(W2s + j0 + 4 * q);
        part = fmaf(tanhf(a[q].x), w4.x, part);
        part = fmaf(tanhf(a[q].y), w4.y, part);
        part = fmaf(tanhf(a[q].z), w4.z, part);
        part = fmaf(tanhf(a[q].w), w4.w, part);
    }
    part += __shfl_xor_sync(0xffffffffu, part, 1);
    part += __shfl_xor_sync(0xffffffffu, part, 2);
    if (valid && jg == 0) g_t[g * NROI + nn] = part;
}

__global__ void __launch_bounds__(1024) k_pool2() {
    __shared__ float red[1024];
    int t = threadIdx.x;
    float mx = -3.0e38f;
    for (int i = t; i < NNODE; i += 1024) mx = fmaxf(mx, g_t[i]);
    red[t] = mx;
    __syncthreads();
    for (int o = 512; o > 0; o >>= 1) {
        if (t < o) red[t] = fmaxf(red[t], red[t + o]);
        __syncthreads();
    }
    float M = red[0];
    __syncthreads();
    float s = 0.f;
    for (int i = t; i < NNODE; i += 1024) s += __expf(g_t[i] - M);
    red[t] = s;
    __syncthreads();
    for (int o = 512; o > 0; o >>= 1) {
        if (t < o) red[t] += red[t + o];
        __syncthreads();
    }
    if (t == 0) { g_MS[0] = M; g_MS[1] = red[0]; }
}

__global__ void __launch_bounds__(128) k_pool3(
    const float* __restrict__ l1W, const float* __restrict__ l1b,
    const float* __restrict__ l2W, const float* __restrict__ l2b,
    float* __restrict__ out)
{
    __shared__ float wex[NROI];
    __shared__ float pooled[HID];
    __shared__ float y[NROI];
    int g = blockIdx.x, t = threadIdx.x;
    float M = g_MS[0];
    float invS = 1.f / g_MS[1];
    if (t < NROI) wex[t] = __expf(g_t[g * NROI + t] - M) * invS;
    __syncthreads();
    if (t < HID) {
        float s = 0.f;
        const float* hg = g_hA + (size_t)g * NROI * HID;
        for (int n = 0; n < NROI; n++) s = fmaf(hg[n * HID + t], wex[n], s);
        pooled[t] = s;
    }
    __syncthreads();
    if (t < NROI) {
        float a = l1b[t];
        for (int c = 0; c < HID; c++) a = fmaf(pooled[c], l1W[c * INCH + t], a);
        y[t] = fmaxf(a, 0.f);
    }
    __syncthreads();
    if (t < 2) {
        float o = l2b[t];
        for (int j = 0; j < NROI; j++) o = fmaf(y[j], l2W[j * 2 + t], o);
        out[g * 2 + t] = o;
    }
}

extern "C" void kernel_launch(void* const* d_in, const int* in_sizes, int n_in,
                              void* d_out, int out_size)
{
    const float* x    = (const float*)d_in[0];
    const float* ea   = (const float*)d_in[1];
    const float* emb  = (const float*)d_in[2];
    const float* encW = (const float*)d_in[3];
    const float* encb = (const float*)d_in[4];
    const float* bng  = (const float*)d_in[5];
    const float* bnb  = (const float*)d_in[6];
    const float* gWe  = (const float*)d_in[7];
    const float* gbe  = (const float*)d_in[8];
    const float* gW1  = (const float*)d_in[9];
    const float* gb1  = (const float*)d_in[10];
    const float* gW2  = (const float*)d_in[11];
    const float* gb2  = (const float*)d_in[12];
    const float* aWl  = (const float*)d_in[13];
    const float* abl  = (const float*)d_in[14];
    const float* aWr  = (const float*)d_in[15];
    const float* abr  = (const float*)d_in[16];
    const float* aat  = (const float*)d_in[17];
    const float* aWe  = (const float*)d_in[18];
    const float* abi  = (const float*)d_in[19];
    const float* pW1  = (const float*)d_in[20];
    const float* pb1  = (const float*)d_in[21];
    const float* pw2  = (const float*)d_in[22];
    const float* l1W  = (const float*)d_in[23];
    const float* l1b  = (const float*)d_in[24];
    const float* l2W  = (const float*)d_in[25];
    const float* l2b  = (const float*)d_in[26];
    const int*   gid  = (const int*)d_in[29];
    float* out = (float*)d_out;

    const int smEnc  = (NROI * CIN + CIN * HID + NROI * RS + HID) * 4;
    const int smGine = (2 * NROI * RS + 2 * HID * HID + EDIM * HID + 2 * ESFC + 3 * HID) * 4;
    const int smGat  = (3 * NROI * RS + HID * HID + EDIM * HID + 2 * ESFC + 3 * HID) * 4;
    cudaFuncSetAttribute(k_encode, cudaFuncAttributeMaxDynamicSharedMemorySize, smEnc);
    cudaFuncSetAttribute(k_gine,   cudaFuncAttributeMaxDynamicSharedMemorySize, smGine);
    cudaFuncSetAttribute(k_gat,    cudaFuncAttributeMaxDynamicSharedMemorySize, smGat);

    k_init<<<1, 64>>>();
    k_encode<<<NGR, THR, smEnc>>>(x, emb, gid, encW, encb);
    k_bnfin<<<1, 64>>>(bng, bnb);
    k_gine<<<NGR, GTHR, smGine>>>(ea, gWe, gbe, gW1, gb1, gW2, gb2);
    k_gat<<<NGR, GTHR, smGat>>>(0, ea, aWl, abl, aWr, abr, aat, aWe, abi);
    k_gat<<<NGR, GTHR, smGat>>>(1, ea, aWl, abl, aWr, abr, aat, aWe, abi);
    k_pool1<<<NGR, 512>>>(pW1, pb1, pw2);
    k_pool2<<<1, 1024>>>();
    k_pool3<<<NGR, 128>>>(l1W, l1b, l2W, l2b, out);
}

// round 14
// speedup vs baseline: 1.0806x; 1.0806x over previous
#include <cuda_runtime.h>
#include <math.h>

#define NROI 116
#define NGR  128
#define HID  64
#define EDIM 5
#define INCH 116
#define EMBD 16
#define CIN  (INCH + EMBD)
#define EPG  (NROI * NROI)
#define NNODE (NROI * NGR)
#define RS   68
#define THR  928
#define GTHR 512
#define CH   29
#define NCHUNK 4
#define ESF  (CH * NROI * EDIM)
#define ESF4 (ESF / 4)

typedef unsigned long long u64;

__device__ float g_hpre[NNODE * HID];
__device__ float g_hA[NNODE * HID];
__device__ float g_sum[HID];
__device__ float g_sumsq[HID];
__device__ float g_scale[HID];
__device__ float g_shift[HID];
__device__ float g_t[NNODE];
__device__ float g_MS[2];

__device__ __forceinline__ float4 ld4(const float* p) { return *reinterpret_cast<const float4*>(p); }
__device__ __forceinline__ void st4(float* p, float4 v) { *reinterpret_cast<float4*>(p) = v; }
__device__ __forceinline__ float4 fma4(float a, float4 b, float4 c) {
    c.x = fmaf(a, b.x, c.x); c.y = fmaf(a, b.y, c.y);
    c.z = fmaf(a, b.z, c.z); c.w = fmaf(a, b.w, c.w); return c;
}
__device__ __forceinline__ float4 add4(float4 a, float4 b) {
    a.x += b.x; a.y += b.y; a.z += b.z; a.w += b.w; return a;
}
__device__ __forceinline__ float4 relu4(float4 a) {
    a.x = fmaxf(a.x, 0.f); a.y = fmaxf(a.y, 0.f);
    a.z = fmaxf(a.z, 0.f); a.w = fmaxf(a.w, 0.f); return a;
}
__device__ __forceinline__ float4 scale4(float4 a, float f) {
    a.x *= f; a.y *= f; a.z *= f; a.w *= f; return a;
}
__device__ __forceinline__ float4 zero4() { return make_float4(0.f, 0.f, 0.f, 0.f); }

__device__ __forceinline__ u64 pk2(float x, float y) {
    u64 r; asm("mov.b64 %0,{%1,%2};" : "=l"(r) : "f"(x), "f"(y)); return r;
}
__device__ __forceinline__ u64 bc2(float x) { return pk2(x, x); }
__device__ __forceinline__ void up2(u64 v, float& x, float& y) {
    asm("mov.b64 {%0,%1},%2;" : "=f"(x), "=f"(y) : "l"(v));
}
__device__ __forceinline__ u64 f2fma(u64 a, u64 b, u64 c) {
    u64 r; asm("fma.rn.f32x2 %0,%1,%2,%3;" : "=l"(r) : "l"(a), "l"(b), "l"(c)); return r;
}
__device__ __forceinline__ void ld4p(const float* p, u64& a, u64& b) {
    float4 v = ld4(p); a = pk2(v.x, v.y); b = pk2(v.z, v.w);
}

__device__ __forceinline__ void cpa16(void* smem_dst, const void* gsrc) {
    unsigned s = (unsigned)__cvta_generic_to_shared(smem_dst);
    asm volatile("cp.async.cg.shared.global [%0], [%1], 16;" :: "r"(s), "l"(gsrc) : "memory");
}
__device__ __forceinline__ void cpa_wait() {
    asm volatile("cp.async.commit_group;" ::: "memory");
    asm volatile("cp.async.wait_group 0;" ::: "memory");
}

__global__ void k_init() {
    int t = threadIdx.x;
    if (t < HID) { g_sum[t] = 0.f; g_sumsq[t] = 0.f; }
}

__global__ void __launch_bounds__(THR) k_encode(
    const float* __restrict__ x, const float* __restrict__ emb,
    const int* __restrict__ gid,
    const float* __restrict__ W, const float* __restrict__ b)
{
    extern __shared__ float sm[];
    float* XC = sm;
    float* WE = XC + NROI * CIN;
    float* HS = WE + CIN * HID;
    float* BS = HS + NROI * RS;
    int g = blockIdx.x, tid = threadIdx.x;

    for (int i = tid; i < CIN * HID; i += THR) WE[i] = W[i];
    if (tid < HID) BS[tid] = b[tid];
    const float* xg = x + (size_t)g * NROI * INCH;
    for (int i = tid; i < NROI * INCH; i += THR) {
        int n = i / INCH, c = i - n * INCH;
        XC[n * CIN + c] = xg[i];
    }
    for (int i = tid; i < NROI * EMBD; i += THR) {
        int n = i / EMBD, k = i - n * EMBD;
        XC[n * CIN + INCH + k] = emb[gid[g * NROI + n] * EMBD + k];
    }
    __syncthreads();

    int n = tid >> 3, jg = tid & 7, j0 = jg * 8;
    {
        float4 a0 = ld4(BS + j0), a1 = ld4(BS + j0 + 4);
        const float* xr = XC + n * CIN;
        #pragma unroll 4
        for (int c = 0; c < CIN; c++) {
            float xv = xr[c];
            const float* wr = WE + c * HID + j0;
            a0 = fma4(xv, ld4(wr), a0);
            a1 = fma4(xv, ld4(wr + 4), a1);
        }
        a0 = relu4(a0); a1 = relu4(a1);
        float* hp = g_hpre + ((size_t)g * NROI + n) * HID + j0;
        float* hs = HS + n * RS + j0;
        st4(hp, a0); st4(hp + 4, a1);
        st4(hs, a0); st4(hs + 4, a1);
    }
    __syncthreads();

    if (tid < HID) {
        float s1 = 0.f, s2 = 0.f;
        for (int r = 0; r < NROI; r++) {
            float v = HS[r * RS + tid];
            s1 += v; s2 += v * v;
        }
        atomicAdd(&g_sum[tid], s1);
        atomicAdd(&g_sumsq[tid], s2);
    }
}

__global__ void k_bnfin(const float* __restrict__ gg, const float* __restrict__ gb) {
    int j = threadIdx.x;
    if (j < HID) {
        const float invN = 1.0f / (float)NNODE;
        float mu  = g_sum[j] * invN;
        float var = g_sumsq[j] * invN - mu * mu;
        float sc  = gg[j] * rsqrtf(var + 1e-5f);
        g_scale[j] = sc;
        g_shift[j] = gb[j] - mu * sc;
    }
}

// =================== FUSED: GINE + GAT x2 + pool1 per graph ================
__global__ void __launch_bounds__(GTHR) k_fused(
    const float* __restrict__ ea,
    const float* __restrict__ gWe, const float* __restrict__ gbe,
    const float* __restrict__ gW1, const float* __restrict__ gb1,
    const float* __restrict__ gW2, const float* __restrict__ gb2,
    const float* __restrict__ aWl, const float* __restrict__ abl,
    const float* __restrict__ aWr, const float* __restrict__ abr,
    const float* __restrict__ aat, const float* __restrict__ aWe,
    const float* __restrict__ abi,
    const float* __restrict__ pW1, const float* __restrict__ pb1,
    const float* __restrict__ pw2)
{
    extern __shared__ float sm[];
    float* H   = sm;                    // NROI*RS
    float* XL  = H + NROI * RS;         // NROI*RS (also AG)
    float* XR  = XL + NROI * RS;        // NROI*RS (also MLP temp)
    float* W1s = XR + NROI * RS;        // HID*HID (gine W1 / gat Wl,Wr / pool W1)
    float* W2s = W1s + HID * HID;       // HID*HID (gine W2)
    float* WEs = W2s + HID * HID;       // EDIM*HID
    float* ES  = WEs + EDIM * HID;      // ESF
    float* BEs = ES + ESF;              // HID
    float* B1s = BEs + HID;             // HID
    float* B2s = B1s + HID;             // HID
    float* ATT = B2s + HID;             // HID
    float* BV  = ATT + HID;             // HID
    float* BI  = BV + HID;              // HID
    int g = blockIdx.x, tid = threadIdx.x;

    int dl = tid >> 3, jg = tid & 7, j0 = jg * 8;
    int d0 = (dl < 58) ? dl : 57;
    int d1 = d0 + 58;
    const float4* eaq = reinterpret_cast<const float4*>(ea + (size_t)g * EPG * EDIM);
    float4* es4 = reinterpret_cast<float4*>(ES);

    // ---------------- Phase A: GINE ----------------
    for (int i = tid; i < HID * HID; i += GTHR) { W1s[i] = gW1[i]; W2s[i] = gW2[i]; }
    if (tid < EDIM * HID) WEs[tid] = gWe[tid];
    if (tid < HID) { BEs[tid] = gbe[tid]; B1s[tid] = gb1[tid]; B2s[tid] = gb2[tid]; }
    const float* hp = g_hpre + (size_t)g * NROI * HID;
    for (int i = tid; i < NROI * HID; i += GTHR) {
        int n = i >> 6, j = i & 63;
        H[n * RS + j] = hp[i] * g_scale[j] + g_shift[j] + __ldg(gbe + j);
    }
    __syncthreads();

    {
        u64 W00, W01, W02, W03, W10, W11, W12, W13, W20, W21, W22, W23,
            W30, W31, W32, W33, W40, W41, W42, W43;
        ld4p(WEs + 0 * HID + j0, W00, W01); ld4p(WEs + 0 * HID + j0 + 4, W02, W03);
        ld4p(WEs + 1 * HID + j0, W10, W11); ld4p(WEs + 1 * HID + j0 + 4, W12, W13);
        ld4p(WEs + 2 * HID + j0, W20, W21); ld4p(WEs + 2 * HID + j0 + 4, W22, W23);
        ld4p(WEs + 3 * HID + j0, W30, W31); ld4p(WEs + 3 * HID + j0 + 4, W32, W33);
        ld4p(WEs + 4 * HID + j0, W40, W41); ld4p(WEs + 4 * HID + j0 + 4, W42, W43);

        float4 accA0 = zero4(), accA1 = zero4(), accB0 = zero4(), accB1 = zero4();

        for (int c = 0; c < NCHUNK; c++) {
            const float4* src = eaq + c * ESF4;
            for (int i = tid; i < ESF4; i += GTHR) cpa16(es4 + i, src + i);
            cpa_wait();
            __syncthreads();

            const float* eroA = ES + d0 * EDIM;
            const float* eroB = ES + d1 * EDIM;
            const float* hr = H + j0 + (c * CH) * RS;
            float a0 = eroA[0], a1 = eroA[1], a2 = eroA[2], a3 = eroA[3], a4 = eroA[4];
            float b0 = eroB[0], b1 = eroB[1], b2 = eroB[2], b3 = eroB[3], b4 = eroB[4];

            #pragma unroll 1
            for (int sl = 0; sl < CH; sl++) {
                int adv = (sl + 1 < CH) ? NROI * EDIM : 0;
                const float* nA = eroA + adv;
                const float* nB = eroB + adv;
                float na0 = nA[0], na1 = nA[1], na2 = nA[2], na3 = nA[3], na4 = nA[4];
                float nb0 = nB[0], nb1 = nB[1], nb2 = nB[2], nb3 = nB[3], nb4 = nB[4];
                float4 h0 = ld4(hr), h1 = ld4(hr + 4);

                u64 E0 = bc2(a0), E1 = bc2(a1), E2 = bc2(a2), E3 = bc2(a3), E4 = bc2(a4);
                u64 pA0 = f2fma(E0, W00, 0ull), pA1 = f2fma(E0, W01, 0ull);
                u64 pA2 = f2fma(E0, W02, 0ull), pA3 = f2fma(E0, W03, 0ull);
                pA0 = f2fma(E1, W10, pA0); pA1 = f2fma(E1, W11, pA1);
                pA2 = f2fma(E1, W12, pA2); pA3 = f2fma(E1, W13, pA3);
                pA0 = f2fma(E2, W20, pA0); pA1 = f2fma(E2, W21, pA1);
                pA2 = f2fma(E2, W22, pA2); pA3 = f2fma(E2, W23, pA3);
                pA0 = f2fma(E3, W30, pA0); pA1 = f2fma(E3, W31, pA1);
                pA2 = f2fma(E3, W32, pA2); pA3 = f2fma(E3, W33, pA3);
                pA0 = f2fma(E4, W40, pA0); pA1 = f2fma(E4, W41, pA1);
                pA2 = f2fma(E4, W42, pA2); pA3 = f2fma(E4, W43, pA3);

                u64 F0 = bc2(b0), F1 = bc2(b1), F2 = bc2(b2), F3 = bc2(b3), F4 = bc2(b4);
                u64 pB0 = f2fma(F0, W00, 0ull), pB1 = f2fma(F0, W01, 0ull);
                u64 pB2 = f2fma(F0, W02, 0ull), pB3 = f2fma(F0, W03, 0ull);
                pB0 = f2fma(F1, W10, pB0); pB1 = f2fma(F1, W11, pB1);
                pB2 = f2fma(F1, W12, pB2); pB3 = f2fma(F1, W13, pB3);
                pB0 = f2fma(F2, W20, pB0); pB1 = f2fma(F2, W21, pB1);
                pB2 = f2fma(F2, W22, pB2); pB3 = f2fma(F2, W23, pB3);
                pB0 = f2fma(F3, W30, pB0); pB1 = f2fma(F3, W31, pB1);
                pB2 = f2fma(F3, W32, pB2); pB3 = f2fma(F3, W33, pB3);
                pB0 = f2fma(F4, W40, pB0); pB1 = f2fma(F4, W41, pB1);
                pB2 = f2fma(F4, W42, pB2); pB3 = f2fma(F4, W43, pB3);

                float q0, q1, q2, q3, q4, q5, q6, q7;
                up2(pA0, q0, q1); up2(pA1, q2, q3); up2(pA2, q4, q5); up2(pA3, q6, q7);
                accA0.x += fmaxf(h0.x + q0, 0.f); accA0.y += fmaxf(h0.y + q1, 0.f);
                accA0.z += fmaxf(h0.z + q2, 0.f); accA0.w += fmaxf(h0.w + q3, 0.f);
                accA1.x += fmaxf(h1.x + q4, 0.f); accA1.y += fmaxf(h1.y + q5, 0.f);
                accA1.z += fmaxf(h1.z + q6, 0.f); accA1.w += fmaxf(h1.w + q7, 0.f);
                up2(pB0, q0, q1); up2(pB1, q2, q3); up2(pB2, q4, q5); up2(pB3, q6, q7);
                accB0.x += fmaxf(h0.x + q0, 0.f); accB0.y += fmaxf(h0.y + q1, 0.f);
                accB0.z += fmaxf(h0.z + q2, 0.f); accB0.w += fmaxf(h0.w + q3, 0.f);
                accB1.x += fmaxf(h1.x + q4, 0.f); accB1.y += fmaxf(h1.y + q5, 0.f);
                accB1.z += fmaxf(h1.z + q6, 0.f); accB1.w += fmaxf(h1.w + q7, 0.f);

                a0 = na0; a1 = na1; a2 = na2; a3 = na3; a4 = na4;
                b0 = nb0; b1 = nb1; b2 = nb2; b3 = nb3; b4 = nb4;
                eroA = nA; eroB = nB;
                hr += RS;
            }
            __syncthreads();
        }

        if (dl < 58) {
            float4 be0 = ld4(BEs + j0), be1 = ld4(BEs + j0 + 4);
            const float* hdA = H + d0 * RS + j0;
            const float* hdB = H + d1 * RS + j0;
            float* agA = XL + d0 * RS + j0;
            float* agB = XL + d1 * RS + j0;
            float4 t;
            t = ld4(hdA);     st4(agA,     add4(accA0, make_float4(t.x - be0.x, t.y - be0.y, t.z - be0.z, t.w - be0.w)));
            t = ld4(hdA + 4); st4(agA + 4, add4(accA1, make_float4(t.x - be1.x, t.y - be1.y, t.z - be1.z, t.w - be1.w)));
            t = ld4(hdB);     st4(agB,     add4(accB0, make_float4(t.x - be0.x, t.y - be0.y, t.z - be0.z, t.w - be0.w)));
            t = ld4(hdB + 4); st4(agB + 4, add4(accB1, make_float4(t.x - be1.x, t.y - be1.y, t.z - be1.z, t.w - be1.w)));
        }
    }
    __syncthreads();

    // GINE MLP1: XL(AG) -> XR
    #pragma unroll 1
    for (int batch = 0; batch < 2; batch++) {
        int n = (tid >> 3) + batch * 64;
        if (n < NROI) {
            float4 a0 = ld4(B1s + j0), a1 = ld4(B1s + j0 + 4);
            const float* inr = XL + n * RS;
            #pragma unroll 4
            for (int c = 0; c < HID; c++) {
                float xv = inr[c];
                const float* wr = W1s + c * HID + j0;
                a0 = fma4(xv, ld4(wr), a0);
                a1 = fma4(xv, ld4(wr + 4), a1);
            }
            float* o = XR + n * RS + j0;
            st4(o, relu4(a0)); st4(o + 4, relu4(a1));
        }
    }
    __syncthreads();

    // GINE MLP2: XR -> H (h after GINE)
    #pragma unroll 1
    for (int batch = 0; batch < 2; batch++) {
        int n = (tid >> 3) + batch * 64;
        if (n < NROI) {
            float4 a0 = ld4(B2s + j0), a1 = ld4(B2s + j0 + 4);
            const float* inr = XR + n * RS;
            #pragma unroll 4
            for (int c = 0; c < HID; c++) {
                float xv = inr[c];
                const float* wr = W2s + c * HID + j0;
                a0 = fma4(xv, ld4(wr), a0);
                a1 = fma4(xv, ld4(wr + 4), a1);
            }
            float* o = H + n * RS + j0;
            st4(o, relu4(a0)); st4(o + 4, relu4(a1));
        }
    }
    __syncthreads();

    // ---------------- Phase B: GAT layers ----------------
    for (int l = 0; l < 2; l++) {
        const float* Wl  = aWl + l * HID * HID;
        const float* bl  = abl + l * HID;
        const float* Wr  = aWr + l * HID * HID;
        const float* br  = abr + l * HID;
        const float* att = aat + l * HID;
        const float* Wee = aWe + l * EDIM * HID;
        const float* bia = abi + l * HID;

        for (int i = tid; i < HID * HID; i += GTHR) W1s[i] = Wl[i];
        if (tid < EDIM * HID) WEs[tid] = Wee[tid];
        if (tid < HID) { ATT[tid] = att[tid]; BV[tid] = bl[tid]; BI[tid] = bia[tid]; }
        __syncthreads();

        #pragma unroll 1
        for (int batch = 0; batch < 2; batch++) {
            int n = (tid >> 3) + batch * 64;
            if (n < NROI) {
                float4 a0 = ld4(BV + j0), a1 = ld4(BV + j0 + 4);
                const float* hr = H + n * RS;
                #pragma unroll 4
                for (int c = 0; c < HID; c++) {
                    float xv = hr[c];
                    const float* wr = W1s + c * HID + j0;
                    a0 = fma4(xv, ld4(wr), a0);
                    a1 = fma4(xv, ld4(wr + 4), a1);
                }
                float* o = XL + n * RS + j0;
                st4(o, a0); st4(o + 4, a1);
            }
        }
        __syncthreads();
        for (int i = tid; i < HID * HID; i += GTHR) W1s[i] = Wr[i];
        if (tid < HID) BV[tid] = br[tid];
        __syncthreads();
        #pragma unroll 1
        for (int batch = 0; batch < 2; batch++) {
            int n = (tid >> 3) + batch * 64;
            if (n < NROI) {
                float4 a0 = ld4(BV + j0), a1 = ld4(BV + j0 + 4);
                const float* hr = H + n * RS;
                #pragma unroll 4
                for (int c = 0; c < HID; c++) {
                    float xv = hr[c];
                    const float* wr = W1s + c * HID + j0;
                    a0 = fma4(xv, ld4(wr), a0);
                    a1 = fma4(xv, ld4(wr + 4), a1);
                }
                float* o = XR + n * RS + j0;
                st4(o, a0); st4(o + 4, a1);
            }
        }
        __syncthreads();

        u64 W00, W01, W02, W03, W10, W11, W12, W13, W20, W21, W22, W23,
            W30, W31, W32, W33, W40, W41, W42, W43;
        ld4p(WEs + 0 * HID + j0, W00, W01); ld4p(WEs + 0 * HID + j0 + 4, W02, W03);
        ld4p(WEs + 1 * HID + j0, W10, W11); ld4p(WEs + 1 * HID + j0 + 4, W12, W13);
        ld4p(WEs + 2 * HID + j0, W20, W21); ld4p(WEs + 2 * HID + j0 + 4, W22, W23);
        ld4p(WEs + 3 * HID + j0, W30, W31); ld4p(WEs + 3 * HID + j0 + 4, W32, W33);
        ld4p(WEs + 4 * HID + j0, W40, W41); ld4p(WEs + 4 * HID + j0 + 4, W42, W43);

        float4 at0 = ld4(ATT + j0), at1 = ld4(ATT + j0 + 4);
        float4 xa0 = ld4(XR + d0 * RS + j0), xa1 = ld4(XR + d0 * RS + j0 + 4);
        float4 xb0 = ld4(XR + d1 * RS + j0), xb1 = ld4(XR + d1 * RS + j0 + 4);
        float4 accA0 = zero4(), accA1 = zero4(), accB0 = zero4(), accB1 = zero4();
        float mA = -3.0e38f, swA = 0.f, mB = -3.0e38f, swB = 0.f;

        for (int c = 0; c < NCHUNK; c++) {
            const float4* src = eaq + c * ESF4;
            for (int i = tid; i < ESF4; i += GTHR) cpa16(es4 + i, src + i);
            cpa_wait();
            __syncthreads();

            const float* eroA = ES + d0 * EDIM;
            const float* eroB = ES + d1 * EDIM;
            const float* xlp = XL + j0 + (c * CH) * RS;
            float a0 = eroA[0], a1 = eroA[1], a2 = eroA[2], a3 = eroA[3], a4 = eroA[4];
            float b0 = eroB[0], b1 = eroB[1], b2 = eroB[2], b3 = eroB[3], b4 = eroB[4];

            #pragma unroll 1
            for (int sl = 0; sl < CH; sl++) {
                int adv = (sl + 1 < CH) ? NROI * EDIM : 0;
                const float* nA = eroA + adv;
                const float* nB = eroB + adv;
                float na0 = nA[0], na1 = nA[1], na2 = nA[2], na3 = nA[3], na4 = nA[4];
                float nb0 = nB[0], nb1 = nB[1], nb2 = nB[2], nb3 = nB[3], nb4 = nB[4];
                float4 xl0 = ld4(xlp), xl1 = ld4(xlp + 4);

                u64 E0 = bc2(a0), E1 = bc2(a1), E2 = bc2(a2), E3 = bc2(a3), E4 = bc2(a4);
                u64 pA0 = f2fma(E0, W00, 0ull), pA1 = f2fma(E0, W01, 0ull);
                u64 pA2 = f2fma(E0, W02, 0ull), pA3 = f2fma(E0, W03, 0ull);
                pA0 = f2fma(E1, W10, pA0); pA1 = f2fma(E1, W11, pA1);
                pA2 = f2fma(E1, W12, pA2); pA3 = f2fma(E1, W13, pA3);
                pA0 = f2fma(E2, W20, pA0); pA1 = f2fma(E2, W21, pA1);
                pA2 = f2fma(E2, W22, pA2); pA3 = f2fma(E2, W23, pA3);
                pA0 = f2fma(E3, W30, pA0); pA1 = f2fma(E3, W31, pA1);
                pA2 = f2fma(E3, W32, pA2); pA3 = f2fma(E3, W33, pA3);
                pA0 = f2fma(E4, W40, pA0); pA1 = f2fma(E4, W41, pA1);
                pA2 = f2fma(E4, W42, pA2); pA3 = f2fma(E4, W43, pA3);

                u64 F0 = bc2(b0), F1 = bc2(b1), F2 = bc2(b2), F3 = bc2(b3), F4 = bc2(b4);
                u64 pB0 = f2fma(F0, W00, 0ull), pB1 = f2fma(F0, W01, 0ull);
                u64 pB2 = f2fma(F0, W02, 0ull), pB3 = f2fma(F0, W03, 0ull);
                pB0 = f2fma(F1, W10, pB0); pB1 = f2fma(F1, W11, pB1);
                pB2 = f2fma(F1, W12, pB2); pB3 = f2fma(F1, W13, pB3);
                pB0 = f2fma(F2, W20, pB0); pB1 = f2fma(F2, W21, pB1);
                pB2 = f2fma(F2, W22, pB2); pB3 = f2fma(F2, W23, pB3);
                pB0 = f2fma(F3, W30, pB0); pB1 = f2fma(F3, W31, pB1);
                pB2 = f2fma(F3, W32, pB2); pB3 = f2fma(F3, W33, pB3);
                pB0 = f2fma(F4, W40, pB0); pB1 = f2fma(F4, W41, pB1);
                pB2 = f2fma(F4, W42, pB2); pB3 = f2fma(F4, W43, pB3);

                float q0, q1, q2, q3, q4, q5, q6, q7;
                float u, pA = 0.f, pB = 0.f;
                up2(pA0, q0, q1); up2(pA1, q2, q3); up2(pA2, q4, q5); up2(pA3, q6, q7);
                u = xl0.x + xa0.x + q0; pA = fmaf(at0.x, fmaxf(u, 0.f) + 0.2f * fminf(u, 0.f), pA);
                u = xl0.y + xa0.y + q1; pA = fmaf(at0.y, fmaxf(u, 0.f) + 0.2f * fminf(u, 0.f), pA);
                u = xl0.z + xa0.z + q2; pA = fmaf(at0.z, fmaxf(u, 0.f) + 0.2f * fminf(u, 0.f), pA);
                u = xl0.w + xa0.w + q3; pA = fmaf(at0.w, fmaxf(u, 0.f) + 0.2f * fminf(u, 0.f), pA);
                u = xl1.x + xa1.x + q4; pA = fmaf(at1.x, fmaxf(u, 0.f) + 0.2f * fminf(u, 0.f), pA);
                u = xl1.y + xa1.y + q5; pA = fmaf(at1.y, fmaxf(u, 0.f) + 0.2f * fminf(u, 0.f), pA);
                u = xl1.z + xa1.z + q6; pA = fmaf(at1.z, fmaxf(u, 0.f) + 0.2f * fminf(u, 0.f), pA);
                u = xl1.w + xa1.w + q7; pA = fmaf(at1.w, fmaxf(u, 0.f) + 0.2f * fminf(u, 0.f), pA);
                up2(pB0, q0, q1); up2(pB1, q2, q3); up2(pB2, q4, q5); up2(pB3, q6, q7);
                u = xl0.x + xb0.x + q0; pB = fmaf(at0.x, fmaxf(u, 0.f) + 0.2f * fminf(u, 0.f), pB);
                u = xl0.y + xb0.y + q1; pB = fmaf(at0.y, fmaxf(u, 0.f) + 0.2f * fminf(u, 0.f), pB);
                u = xl0.z + xb0.z + q2; pB = fmaf(at0.z, fmaxf(u, 0.f) + 0.2f * fminf(u, 0.f), pB);
                u = xl0.w + xb0.w + q3; pB = fmaf(at0.w, fmaxf(u, 0.f) + 0.2f * fminf(u, 0.f), pB);
                u = xl1.x + xb1.x + q4; pB = fmaf(at1.x, fmaxf(u, 0.f) + 0.2f * fminf(u, 0.f), pB);
                u = xl1.y + xb1.y + q5; pB = fmaf(at1.y, fmaxf(u, 0.f) + 0.2f * fminf(u, 0.f), pB);
                u = xl1.z + xb1.z + q6; pB = fmaf(at1.z, fmaxf(u, 0.f) + 0.2f * fminf(u, 0.f), pB);
                u = xl1.w + xb1.w + q7; pB = fmaf(at1.w, fmaxf(u, 0.f) + 0.2f * fminf(u, 0.f), pB);

                pA += __shfl_xor_sync(0xffffffffu, pA, 1);
                pB += __shfl_xor_sync(0xffffffffu, pB, 1);
                pA += __shfl_xor_sync(0xffffffffu, pA, 2);
                pB += __shfl_xor_sync(0xffffffffu, pB, 2);
                pA += __shfl_xor_sync(0xffffffffu, pA, 4);
                pB += __shfl_xor_sync(0xffffffffu, pB, 4);

                float wA;
                if (pA <= mA) {
                    wA = __expf(pA - mA);
                } else {
                    float fac = __expf(mA - pA);
                    swA *= fac;
                    accA0 = scale4(accA0, fac); accA1 = scale4(accA1, fac);
                    mA = pA;
                    wA = 1.f;
                }
                swA += wA;
                accA0 = fma4(wA, xl0, accA0);
                accA1 = fma4(wA, xl1, accA1);

                float wB;
                if (pB <= mB) {
                    wB = __expf(pB - mB);
                } else {
                    float fac = __expf(mB - pB);
                    swB *= fac;
                    accB0 = scale4(accB0, fac); accB1 = scale4(accB1, fac);
                    mB = pB;
                    wB = 1.f;
                }
                swB += wB;
                accB0 = fma4(wB, xl0, accB0);
                accB1 = fma4(wB, xl1, accB1);

                a0 = na0; a1 = na1; a2 = na2; a3 = na3; a4 = na4;
                b0 = nb0; b1 = nb1; b2 = nb2; b3 = nb3; b4 = nb4;
                eroA = nA; eroB = nB;
                xlp += RS;
            }
            __syncthreads();
        }

        if (dl < 58) {
            float4 bi0 = ld4(BI + j0), bi1 = ld4(BI + j0 + 4);
            float invA = 1.f / (swA + 1e-16f);
            float invB = 1.f / (swB + 1e-16f);
            float4 oA0 = relu4(add4(scale4(accA0, invA), bi0));
            float4 oA1 = relu4(add4(scale4(accA1, invA), bi1));
            float4 oB0 = relu4(add4(scale4(accB0, invB), bi0));
            float4 oB1 = relu4(add4(scale4(accB1, invB), bi1));
            float* hA = H + d0 * RS + j0;
            float* hB = H + d1 * RS + j0;
            st4(hA, oA0); st4(hA + 4, oA1);
            st4(hB, oB0); st4(hB + 4, oB1);
            if (l == 1) {
                float* gA = g_hA + ((size_t)g * NROI + d0) * HID + j0;
                float* gB = g_hA + ((size_t)g * NROI + d1) * HID + j0;
                st4(gA, oA0); st4(gA + 4, oA1);
                st4(gB, oB0); st4(gB + 4, oB1);
            }
        }
        __syncthreads();
    }

    // ---------------- Phase C: pool1 (t[n] from smem H) ----------------
    for (int i = tid; i < HID * HID; i += GTHR) W1s[i] = pW1[i];
    if (tid < HID) { BV[tid] = pb1[tid]; ATT[tid] = pw2[tid]; }
    __syncthreads();

    {
        float4 w20 = ld4(ATT + j0), w21 = ld4(ATT + j0 + 4);
        #pragma unroll 1
        for (int which = 0; which < 2; which++) {
            int d = which ? d1 : d0;
            float4 a0 = ld4(BV + j0), a1 = ld4(BV + j0 + 4);
            const float* hr = H + d * RS;
            #pragma unroll 4
            for (int c = 0; c < HID; c++) {
                float xv = hr[c];
                const float* wr = W1s + c * HID + j0;
                a0 = fma4(xv, ld4(wr), a0);
                a1 = fma4(xv, ld4(wr + 4), a1);
            }
            float part = 0.f;
            part = fmaf(tanhf(a0.x), w20.x, part);
            part = fmaf(tanhf(a0.y), w20.y, part);
            part = fmaf(tanhf(a0.z), w20.z, part);
            part = fmaf(tanhf(a0.w), w20.w, part);
            part = fmaf(tanhf(a1.x), w21.x, part);
            part = fmaf(tanhf(a1.y), w21.y, part);
            part = fmaf(tanhf(a1.z), w21.z, part);
            part = fmaf(tanhf(a1.w), w21.w, part);
            part += __shfl_xor_sync(0xffffffffu, part, 1);
            part += __shfl_xor_sync(0xffffffffu, part, 2);
            part += __shfl_xor_sync(0xffffffffu, part, 4);
            if (dl < 58 && jg == 0) g_t[g * NROI + d] = part;
        }
    }
}

__global__ void __launch_bounds__(1024) k_pool2() {
    __shared__ float red[1024];
    int t = threadIdx.x;
    float mx = -3.0e38f;
    for (int i = t; i < NNODE; i += 1024) mx = fmaxf(mx, g_t[i]);
    red[t] = mx;
    __syncthreads();
    for (int o = 512; o > 0; o >>= 1) {
        if (t < o) red[t] = fmaxf(red[t], red[t + o]);
        __syncthreads();
    }
    float M = red[0];
    __syncthreads();
    float s = 0.f;
    for (int i = t; i < NNODE; i += 1024) s += __expf(g_t[i] - M);
    red[t] = s;
    __syncthreads();
    for (int o = 512; o > 0; o >>= 1) {
        if (t < o) red[t] += red[t + o];
        __syncthreads();
    }
    if (t == 0) { g_MS[0] = M; g_MS[1] = red[0]; }
}

__global__ void __launch_bounds__(128) k_pool3(
    const float* __restrict__ l1W, const float* __restrict__ l1b,
    const float* __restrict__ l2W, const float* __restrict__ l2b,
    float* __restrict__ out)
{
    __shared__ float wex[NROI];
    __shared__ float pooled[HID];
    __shared__ float y[NROI];
    int g = blockIdx.x, t = threadIdx.x;
    float M = g_MS[0];
    float invS = 1.f / g_MS[1];
    if (t < NROI) wex[t] = __expf(g_t[g * NROI + t] - M) * invS;
    __syncthreads();
    if (t < HID) {
        float s = 0.f;
        const float* hg = g_hA + (size_t)g * NROI * HID;
        for (int n = 0; n < NROI; n++) s = fmaf(hg[n * HID + t], wex[n], s);
        pooled[t] = s;
    }
    __syncthreads();
    if (t < NROI) {
        float a = l1b[t];
        for (int c = 0; c < HID; c++) a = fmaf(pooled[c], l1W[c * INCH + t], a);
        y[t] = fmaxf(a, 0.f);
    }
    __syncthreads();
    if (t < 2) {
        float o = l2b[t];
        for (int j = 0; j < NROI; j++) o = fmaf(y[j], l2W[j * 2 + t], o);
        out[g * 2 + t] = o;
    }
}

extern "C" void kernel_launch(void* const* d_in, const int* in_sizes, int n_in,
                              void* d_out, int out_size)
{
    const float* x    = (const float*)d_in[0];
    const float* ea   = (const float*)d_in[1];
    const float* emb  = (const float*)d_in[2];
    const float* encW = (const float*)d_in[3];
    const float* encb = (const float*)d_in[4];
    const float* bng  = (const float*)d_in[5];
    const float* bnb  = (const float*)d_in[6];
    const float* gWe  = (const float*)d_in[7];
    const float* gbe  = (const float*)d_in[8];
    const float* gW1  = (const float*)d_in[9];
    const float* gb1  = (const float*)d_in[10];
    const float* gW2  = (const float*)d_in[11];
    const float* gb2  = (const float*)d_in[12];
    const float* aWl  = (const float*)d_in[13];
    const float* abl  = (const float*)d_in[14];
    const float* aWr  = (const float*)d_in[15];
    const float* abr  = (const float*)d_in[16];
    const float* aat  = (const float*)d_in[17];
    const float* aWe  = (const float*)d_in[18];
    const float* abi  = (const float*)d_in[19];
    const float* pW1  = (const float*)d_in[20];
    const float* pb1  = (const float*)d_in[21];
    const float* pw2  = (const float*)d_in[22];
    const float* l1W  = (const float*)d_in[23];
    const float* l1b  = (const float*)d_in[24];
    const float* l2W  = (const float*)d_in[25];
    const float* l2b  = (const float*)d_in[26];
    const int*   gid  = (const int*)d_in[29];
    float* out = (float*)d_out;

    const int smEnc = (NROI * CIN + CIN * HID + NROI * RS + HID) * 4;
    const int smFus = (3 * NROI * RS + 2 * HID * HID + EDIM * HID + ESF + 6 * HID) * 4;
    cudaFuncSetAttribute(k_encode, cudaFuncAttributeMaxDynamicSharedMemorySize, smEnc);
    cudaFuncSetAttribute(k_fused,  cudaFuncAttributeMaxDynamicSharedMemorySize, smFus);

    k_init<<<1, 64>>>();
    k_encode<<<NGR, THR, smEnc>>>(x, emb, gid, encW, encb);
    k_bnfin<<<1, 64>>>(bng, bnb);
    k_fused<<<NGR, GTHR, smFus>>>(ea, gWe, gbe, gW1, gb1, gW2, gb2,
                                  aWl, abl, aWr, abr, aat, aWe, abi,
                                  pW1, pb1, pw2);
    k_pool2<<<1, 1024>>>();
    k_pool3<<<NGR, 128>>>(l1W, l1b, l2W, l2b, out);
}

// round 16
// speedup vs baseline: 1.1102x; 1.0274x over previous
#include <cuda_runtime.h>
#include <math.h>

#define NROI 116
#define NGR  128
#define HID  64
#define EDIM 5
#define INCH 116
#define EMBD 16
#define CIN  (INCH + EMBD)
#define EPG  (NROI * NROI)
#define NNODE (NROI * NGR)
#define RS   68
#define GTHR 512
#define CH   29
#define NCHUNK 4
#define ESF  (CH * NROI * EDIM)
#define ESF4 (ESF / 4)

typedef unsigned long long u64;

__device__ float g_part1[NGR * HID];
__device__ float g_part2[NGR * HID];
__device__ float g_t[NNODE];
__device__ unsigned g_bar1, g_rel1, g_done1;
__device__ unsigned g_bar2, g_rel2, g_done2;

__device__ __forceinline__ float4 ld4(const float* p) { return *reinterpret_cast<const float4*>(p); }
__device__ __forceinline__ void st4(float* p, float4 v) { *reinterpret_cast<float4*>(p) = v; }
__device__ __forceinline__ float4 fma4(float a, float4 b, float4 c) {
    c.x = fmaf(a, b.x, c.x); c.y = fmaf(a, b.y, c.y);
    c.z = fmaf(a, b.z, c.z); c.w = fmaf(a, b.w, c.w); return c;
}
__device__ __forceinline__ float4 add4(float4 a, float4 b) {
    a.x += b.x; a.y += b.y; a.z += b.z; a.w += b.w; return a;
}
__device__ __forceinline__ float4 relu4(float4 a) {
    a.x = fmaxf(a.x, 0.f); a.y = fmaxf(a.y, 0.f);
    a.z = fmaxf(a.z, 0.f); a.w = fmaxf(a.w, 0.f); return a;
}
__device__ __forceinline__ float4 scale4(float4 a, float f) {
    a.x *= f; a.y *= f; a.z *= f; a.w *= f; return a;
}
__device__ __forceinline__ float4 zero4() { return make_float4(0.f, 0.f, 0.f, 0.f); }

__device__ __forceinline__ u64 pk2(float x, float y) {
    u64 r; asm("mov.b64 %0,{%1,%2};" : "=l"(r) : "f"(x), "f"(y)); return r;
}
__device__ __forceinline__ u64 bc2(float x) { return pk2(x, x); }
__device__ __forceinline__ void up2(u64 v, float& x, float& y) {
    asm("mov.b64 {%0,%1},%2;" : "=f"(x), "=f"(y) : "l"(v));
}
__device__ __forceinline__ u64 f2fma(u64 a, u64 b, u64 c) {
    u64 r; asm("fma.rn.f32x2 %0,%1,%2,%3;" : "=l"(r) : "l"(a), "l"(b), "l"(c)); return r;
}
__device__ __forceinline__ void ld4p(const float* p, u64& a, u64& b) {
    float4 v = ld4(p); a = pk2(v.x, v.y); b = pk2(v.z, v.w);
}

__device__ __forceinline__ void cpa16(void* smem_dst, const void* gsrc) {
    unsigned s = (unsigned)__cvta_generic_to_shared(smem_dst);
    asm volatile("cp.async.cg.shared.global [%0], [%1], 16;" :: "r"(s), "l"(gsrc) : "memory");
}
__device__ __forceinline__ void cpa_wait() {
    asm volatile("cp.async.commit_group;" ::: "memory");
    asm volatile("cp.async.wait_group 0;" ::: "memory");
}

// self-resetting grid barrier; safe: all NGR CTAs co-resident (1 CTA/SM, grid<=SMs)
__device__ __forceinline__ void gridbar(unsigned* bar, unsigned* rel, unsigned* done) {
    __threadfence();
    __syncthreads();
    if (threadIdx.x == 0) {
        unsigned a = atomicAdd(bar, 1u);
        if (a == NGR - 1) {
            atomicExch(rel, 1u);
        } else {
            while (atomicAdd(rel, 0u) == 0u) {}
        }
        __threadfence();
        unsigned d = atomicAdd(done, 1u);
        if (d == NGR - 1) {
            atomicExch(bar, 0u); atomicExch(rel, 0u); atomicExch(done, 0u);
        }
    }
    __syncthreads();
}

// ===== Fully fused kernel: encode+BN+GINE+GATx2+pool+head =====
__global__ void __launch_bounds__(GTHR) k_mega(
    const float* __restrict__ x, const float* __restrict__ ea,
    const float* __restrict__ emb, const int* __restrict__ gid,
    const float* __restrict__ encW, const float* __restrict__ encb,
    const float* __restrict__ bng, const float* __restrict__ bnb,
    const float* __restrict__ gWe, const float* __restrict__ gbe,
    const float* __restrict__ gW1, const float* __restrict__ gb1,
    const float* __restrict__ gW2, const float* __restrict__ gb2,
    const float* __restrict__ aWl, const float* __restrict__ abl,
    const float* __restrict__ aWr, const float* __restrict__ abr,
    const float* __restrict__ aat, const float* __restrict__ aWe,
    const float* __restrict__ abi,
    const float* __restrict__ pW1, const float* __restrict__ pb1,
    const float* __restrict__ pw2,
    const float* __restrict__ l1W, const float* __restrict__ l1b,
    const float* __restrict__ l2W, const float* __restrict__ l2b,
    float* __restrict__ out)
{
    extern __shared__ float sm[];
    float* H   = sm;
    float* XL  = H + NROI * RS;
    float* XR  = XL + NROI * RS;
    float* W1s = XR + NROI * RS;
    float* W2s = W1s + HID * HID;
    float* WEs = W2s + HID * HID;
    float* ES  = WEs + EDIM * HID;
    float* BEs = ES + ESF;
    float* B1s = BEs + HID;
    float* B2s = B1s + HID;
    float* ATT = B2s + HID;
    float* BV  = ATT + HID;
    float* BI  = BV + HID;
    int g = blockIdx.x, tid = threadIdx.x;

    int dl = tid >> 3, jg = tid & 7, j0 = jg * 8;
    int d0 = (dl < 58) ? dl : 57;
    int d1 = d0 + 58;
    const float4* eaq = reinterpret_cast<const float4*>(ea + (size_t)g * EPG * EDIM);
    float4* es4 = reinterpret_cast<float4*>(ES);

    // ---------------- Phase 0: encode ----------------
    {
        float* XC = ES;     // NROI*CIN = 15312 <= ESF (16820)
        float* WE = W1s;    // CIN*HID = 8448 <= W1s+W2s+WEs (8512)
        for (int i = tid; i < CIN * HID; i += GTHR) WE[i] = encW[i];
        if (tid < HID) B1s[tid] = encb[tid];
        const float* xg = x + (size_t)g * NROI * INCH;
        for (int i = tid; i < NROI * INCH; i += GTHR) {
            int n = i / INCH, c = i - n * INCH;
            XC[n * CIN + c] = xg[i];
        }
        for (int i = tid; i < NROI * EMBD; i += GTHR) {
            int n = i / EMBD, k = i - n * EMBD;
            XC[n * CIN + INCH + k] = emb[gid[g * NROI + n] * EMBD + k];
        }
        __syncthreads();

        #pragma unroll 1
        for (int batch = 0; batch < 2; batch++) {
            int n = (tid >> 3) + batch * 64;
            if (n < NROI) {
                float4 a0 = ld4(B1s + j0), a1 = ld4(B1s + j0 + 4);
                const float* xr = XC + n * CIN;
                #pragma unroll 4
                for (int c = 0; c < CIN; c++) {
                    float xv = xr[c];
                    const float* wr = WE + c * HID + j0;
                    a0 = fma4(xv, ld4(wr), a0);
                    a1 = fma4(xv, ld4(wr + 4), a1);
                }
                float* hs = H + n * RS + j0;
                st4(hs, relu4(a0)); st4(hs + 4, relu4(a1));
            }
        }
        __syncthreads();

        if (tid < HID) {
            float s1 = 0.f, s2 = 0.f;
            for (int r = 0; r < NROI; r++) {
                float v = H[r * RS + tid];
                s1 += v; s2 += v * v;
            }
            g_part1[g * HID + tid] = s1;
            g_part2[g * HID + tid] = s2;
        }
    }
    gridbar(&g_bar1, &g_rel1, &g_done1);

    // BN finalize (per CTA, redundant) + transform H in place (+ gbe folded)
    if (tid < HID) {
        float s1 = 0.f, s2 = 0.f;
        for (int q = 0; q < NGR; q++) {
            s1 += g_part1[q * HID + tid];
            s2 += g_part2[q * HID + tid];
        }
        const float invN = 1.0f / (float)NNODE;
        float mu  = s1 * invN;
        float var = s2 * invN - mu * mu;
        float sc  = __ldg(bng + tid) * rsqrtf(var + 1e-5f);
        ATT[tid] = sc;
        BV[tid]  = __ldg(bnb + tid) - mu * sc + __ldg(gbe + tid);
    }
    __syncthreads();
    for (int i = tid; i < NROI * HID; i += GTHR) {
        int n = i >> 6, j = i & 63;
        H[n * RS + j] = H[n * RS + j] * ATT[j] + BV[j];
    }
    __syncthreads();

    // ---------------- Phase A: GINE ----------------
    for (int i = tid; i < HID * HID; i += GTHR) { W1s[i] = gW1[i]; W2s[i] = gW2[i]; }
    if (tid < EDIM * HID) WEs[tid] = gWe[tid];
    if (tid < HID) { BEs[tid] = gbe[tid]; B1s[tid] = gb1[tid]; B2s[tid] = gb2[tid]; }
    __syncthreads();

    {
        u64 W00, W01, W02, W03, W10, W11, W12, W13, W20, W21, W22, W23,
            W30, W31, W32, W33, W40, W41, W42, W43;
        ld4p(WEs + 0 * HID + j0, W00, W01); ld4p(WEs + 0 * HID + j0 + 4, W02, W03);
        ld4p(WEs + 1 * HID + j0, W10, W11); ld4p(WEs + 1 * HID + j0 + 4, W12, W13);
        ld4p(WEs + 2 * HID + j0, W20, W21); ld4p(WEs + 2 * HID + j0 + 4, W22, W23);
        ld4p(WEs + 3 * HID + j0, W30, W31); ld4p(WEs + 3 * HID + j0 + 4, W32, W33);
        ld4p(WEs + 4 * HID + j0, W40, W41); ld4p(WEs + 4 * HID + j0 + 4, W42, W43);

        float4 accA0 = zero4(), accA1 = zero4(), accB0 = zero4(), accB1 = zero4();

        for (int c = 0; c < NCHUNK; c++) {
            const float4* src = eaq + c * ESF4;
            for (int i = tid; i < ESF4; i += GTHR) cpa16(es4 + i, src + i);
            cpa_wait();
            __syncthreads();

            const float* eroA = ES + d0 * EDIM;
            const float* eroB = ES + d1 * EDIM;
            const float* hr = H + j0 + (c * CH) * RS;
            float a0 = eroA[0], a1 = eroA[1], a2 = eroA[2], a3 = eroA[3], a4 = eroA[4];
            float b0 = eroB[0], b1 = eroB[1], b2 = eroB[2], b3 = eroB[3], b4 = eroB[4];

            #pragma unroll 1
            for (int sl = 0; sl < CH; sl++) {
                int adv = (sl + 1 < CH) ? NROI * EDIM : 0;
                const float* nA = eroA + adv;
                const float* nB = eroB + adv;
                float na0 = nA[0], na1 = nA[1], na2 = nA[2], na3 = nA[3], na4 = nA[4];
                float nb0 = nB[0], nb1 = nB[1], nb2 = nB[2], nb3 = nB[3], nb4 = nB[4];
                float4 h0 = ld4(hr), h1 = ld4(hr + 4);

                u64 E0 = bc2(a0), E1 = bc2(a1), E2 = bc2(a2), E3 = bc2(a3), E4 = bc2(a4);
                u64 pA0 = f2fma(E0, W00, 0ull), pA1 = f2fma(E0, W01, 0ull);
                u64 pA2 = f2fma(E0, W02, 0ull), pA3 = f2fma(E0, W03, 0ull);
                pA0 = f2fma(E1, W10, pA0); pA1 = f2fma(E1, W11, pA1);
                pA2 = f2fma(E1, W12, pA2); pA3 = f2fma(E1, W13, pA3);
                pA0 = f2fma(E2, W20, pA0); pA1 = f2fma(E2, W21, pA1);
                pA2 = f2fma(E2, W22, pA2); pA3 = f2fma(E2, W23, pA3);
                pA0 = f2fma(E3, W30, pA0); pA1 = f2fma(E3, W31, pA1);
                pA2 = f2fma(E3, W32, pA2); pA3 = f2fma(E3, W33, pA3);
                pA0 = f2fma(E4, W40, pA0); pA1 = f2fma(E4, W41, pA1);
                pA2 = f2fma(E4, W42, pA2); pA3 = f2fma(E4, W43, pA3);

                u64 F0 = bc2(b0), F1 = bc2(b1), F2 = bc2(b2), F3 = bc2(b3), F4 = bc2(b4);
                u64 pB0 = f2fma(F0, W00, 0ull), pB1 = f2fma(F0, W01, 0ull);
                u64 pB2 = f2fma(F0, W02, 0ull), pB3 = f2fma(F0, W03, 0ull);
                pB0 = f2fma(F1, W10, pB0); pB1 = f2fma(F1, W11, pB1);
                pB2 = f2fma(F1, W12, pB2); pB3 = f2fma(F1, W13, pB3);
                pB0 = f2fma(F2, W20, pB0); pB1 = f2fma(F2, W21, pB1);
                pB2 = f2fma(F2, W22, pB2); pB3 = f2fma(F2, W23, pB3);
                pB0 = f2fma(F3, W30, pB0); pB1 = f2fma(F3, W31, pB1);
                pB2 = f2fma(F3, W32, pB2); pB3 = f2fma(F3, W33, pB3);
                pB0 = f2fma(F4, W40, pB0); pB1 = f2fma(F4, W41, pB1);
                pB2 = f2fma(F4, W42, pB2); pB3 = f2fma(F4, W43, pB3);

                float q0, q1, q2, q3, q4, q5, q6, q7;
                up2(pA0, q0, q1); up2(pA1, q2, q3); up2(pA2, q4, q5); up2(pA3, q6, q7);
                accA0.x += fmaxf(h0.x + q0, 0.f); accA0.y += fmaxf(h0.y + q1, 0.f);
                accA0.z += fmaxf(h0.z + q2, 0.f); accA0.w += fmaxf(h0.w + q3, 0.f);
                accA1.x += fmaxf(h1.x + q4, 0.f); accA1.y += fmaxf(h1.y + q5, 0.f);
                accA1.z += fmaxf(h1.z + q6, 0.f); accA1.w += fmaxf(h1.w + q7, 0.f);
                up2(pB0, q0, q1); up2(pB1, q2, q3); up2(pB2, q4, q5); up2(pB3, q6, q7);
                accB0.x += fmaxf(h0.x + q0, 0.f); accB0.y += fmaxf(h0.y + q1, 0.f);
                accB0.z += fmaxf(h0.z + q2, 0.f); accB0.w += fmaxf(h0.w + q3, 0.f);
                accB1.x += fmaxf(h1.x + q4, 0.f); accB1.y += fmaxf(h1.y + q5, 0.f);
                accB1.z += fmaxf(h1.z + q6, 0.f); accB1.w += fmaxf(h1.w + q7, 0.f);

                a0 = na0; a1 = na1; a2 = na2; a3 = na3; a4 = na4;
                b0 = nb0; b1 = nb1; b2 = nb2; b3 = nb3; b4 = nb4;
                eroA = nA; eroB = nB;
                hr += RS;
            }
            __syncthreads();
        }

        if (dl < 58) {
            float4 be0 = ld4(BEs + j0), be1 = ld4(BEs + j0 + 4);
            const float* hdA = H + d0 * RS + j0;
            const float* hdB = H + d1 * RS + j0;
            float* agA = XL + d0 * RS + j0;
            float* agB = XL + d1 * RS + j0;
            float4 t;
            t = ld4(hdA);     st4(agA,     add4(accA0, make_float4(t.x - be0.x, t.y - be0.y, t.z - be0.z, t.w - be0.w)));
            t = ld4(hdA + 4); st4(agA + 4, add4(accA1, make_float4(t.x - be1.x, t.y - be1.y, t.z - be1.z, t.w - be1.w)));
            t = ld4(hdB);     st4(agB,     add4(accB0, make_float4(t.x - be0.x, t.y - be0.y, t.z - be0.z, t.w - be0.w)));
            t = ld4(hdB + 4); st4(agB + 4, add4(accB1, make_float4(t.x - be1.x, t.y - be1.y, t.z - be1.z, t.w - be1.w)));
        }
    }
    __syncthreads();

    // GINE MLP1: XL(AG) -> XR
    #pragma unroll 1
    for (int batch = 0; batch < 2; batch++) {
        int n = (tid >> 3) + batch * 64;
        if (n < NROI) {
            float4 a0 = ld4(B1s + j0), a1 = ld4(B1s + j0 + 4);
            const float* inr = XL + n * RS;
            #pragma unroll 4
            for (int c = 0; c < HID; c++) {
                float xv = inr[c];
                const float* wr = W1s + c * HID + j0;
                a0 = fma4(xv, ld4(wr), a0);
                a1 = fma4(xv, ld4(wr + 4), a1);
            }
            float* o = XR + n * RS + j0;
            st4(o, relu4(a0)); st4(o + 4, relu4(a1));
        }
    }
    __syncthreads();

    // GINE MLP2: XR -> H
    #pragma unroll 1
    for (int batch = 0; batch < 2; batch++) {
        int n = (tid >> 3) + batch * 64;
        if (n < NROI) {
            float4 a0 = ld4(B2s + j0), a1 = ld4(B2s + j0 + 4);
            const float* inr = XR + n * RS;
            #pragma unroll 4
            for (int c = 0; c < HID; c++) {
                float xv = inr[c];
                const float* wr = W2s + c * HID + j0;
                a0 = fma4(xv, ld4(wr), a0);
                a1 = fma4(xv, ld4(wr + 4), a1);
            }
            float* o = H + n * RS + j0;
            st4(o, relu4(a0)); st4(o + 4, relu4(a1));
        }
    }
    __syncthreads();

    // ---------------- Phase B: GAT layers ----------------
    for (int l = 0; l < 2; l++) {
        const float* Wl  = aWl + l * HID * HID;
        const float* bl  = abl + l * HID;
        const float* Wr  = aWr + l * HID * HID;
        const float* br  = abr + l * HID;
        const float* att = aat + l * HID;
        const float* Wee = aWe + l * EDIM * HID;
        const float* bia = abi + l * HID;

        for (int i = tid; i < HID * HID; i += GTHR) W1s[i] = Wl[i];
        if (tid < EDIM * HID) WEs[tid] = Wee[tid];
        if (tid < HID) { ATT[tid] = att[tid]; BV[tid] = bl[tid]; BI[tid] = bia[tid]; }
        __syncthreads();

        #pragma unroll 1
        for (int batch = 0; batch < 2; batch++) {
            int n = (tid >> 3) + batch * 64;
            if (n < NROI) {
                float4 a0 = ld4(BV + j0), a1 = ld4(BV + j0 + 4);
                const float* hr = H + n * RS;
                #pragma unroll 4
                for (int c = 0; c < HID; c++) {
                    float xv = hr[c];
                    const float* wr = W1s + c * HID + j0;
                    a0 = fma4(xv, ld4(wr), a0);
                    a1 = fma4(xv, ld4(wr + 4), a1);
                }
                float* o = XL + n * RS + j0;
                st4(o, a0); st4(o + 4, a1);
            }
        }
        __syncthreads();
        for (int i = tid; i < HID * HID; i += GTHR) W1s[i] = Wr[i];
        if (tid < HID) BV[tid] = br[tid];
        __syncthreads();
        #pragma unroll 1
        for (int batch = 0; batch < 2; batch++) {
            int n = (tid >> 3) + batch * 64;
            if (n < NROI) {
                float4 a0 = ld4(BV + j0), a1 = ld4(BV + j0 + 4);
                const float* hr = H + n * RS;
                #pragma unroll 4
                for (int c = 0; c < HID; c++) {
                    float xv = hr[c];
                    const float* wr = W1s + c * HID + j0;
                    a0 = fma4(xv, ld4(wr), a0);
                    a1 = fma4(xv, ld4(wr + 4), a1);
                }
                float* o = XR + n * RS + j0;
                st4(o, a0); st4(o + 4, a1);
            }
        }
        __syncthreads();

        u64 W00, W01, W02, W03, W10, W11, W12, W13, W20, W21, W22, W23,
            W30, W31, W32, W33, W40, W41, W42, W43;
        ld4p(WEs + 0 * HID + j0, W00, W01); ld4p(WEs + 0 * HID + j0 + 4, W02, W03);
        ld4p(WEs + 1 * HID + j0, W10, W11); ld4p(WEs + 1 * HID + j0 + 4, W12, W13);
        ld4p(WEs + 2 * HID + j0, W20, W21); ld4p(WEs + 2 * HID + j0 + 4, W22, W23);
        ld4p(WEs + 3 * HID + j0, W30, W31); ld4p(WEs + 3 * HID + j0 + 4, W32, W33);
        ld4p(WEs + 4 * HID + j0, W40, W41); ld4p(WEs + 4 * HID + j0 + 4, W42, W43);

        float4 at0 = ld4(ATT + j0), at1 = ld4(ATT + j0 + 4);
        float4 xa0 = ld4(XR + d0 * RS + j0), xa1 = ld4(XR + d0 * RS + j0 + 4);
        float4 xb0 = ld4(XR + d1 * RS + j0), xb1 = ld4(XR + d1 * RS + j0 + 4);
        float4 accA0 = zero4(), accA1 = zero4(), accB0 = zero4(), accB1 = zero4();
        float mA = -3.0e38f, swA = 0.f, mB = -3.0e38f, swB = 0.f;

        for (int c = 0; c < NCHUNK; c++) {
            const float4* src = eaq + c * ESF4;
            for (int i = tid; i < ESF4; i += GTHR) cpa16(es4 + i, src + i);
            cpa_wait();
            __syncthreads();

            const float* eroA = ES + d0 * EDIM;
            const float* eroB = ES + d1 * EDIM;
            const float* xlp = XL + j0 + (c * CH) * RS;
            float a0 = eroA[0], a1 = eroA[1], a2 = eroA[2], a3 = eroA[3], a4 = eroA[4];
            float b0 = eroB[0], b1 = eroB[1], b2 = eroB[2], b3 = eroB[3], b4 = eroB[4];

            #pragma unroll 1
            for (int sl = 0; sl < CH; sl++) {
                int adv = (sl + 1 < CH) ? NROI * EDIM : 0;
                const float* nA = eroA + adv;
                const float* nB = eroB + adv;
                float na0 = nA[0], na1 = nA[1], na2 = nA[2], na3 = nA[3], na4 = nA[4];
                float nb0 = nB[0], nb1 = nB[1], nb2 = nB[2], nb3 = nB[3], nb4 = nB[4];
                float4 xl0 = ld4(xlp), xl1 = ld4(xlp + 4);

                u64 E0 = bc2(a0), E1 = bc2(a1), E2 = bc2(a2), E3 = bc2(a3), E4 = bc2(a4);
                u64 pA0 = f2fma(E0, W00, 0ull), pA1 = f2fma(E0, W01, 0ull);
                u64 pA2 = f2fma(E0, W02, 0ull), pA3 = f2fma(E0, W03, 0ull);
                pA0 = f2fma(E1, W10, pA0); pA1 = f2fma(E1, W11, pA1);
                pA2 = f2fma(E1, W12, pA2); pA3 = f2fma(E1, W13, pA3);
                pA0 = f2fma(E2, W20, pA0); pA1 = f2fma(E2, W21, pA1);
                pA2 = f2fma(E2, W22, pA2); pA3 = f2fma(E2, W23, pA3);
                pA0 = f2fma(E3, W30, pA0); pA1 = f2fma(E3, W31, pA1);
                pA2 = f2fma(E3, W32, pA2); pA3 = f2fma(E3, W33, pA3);
                pA0 = f2fma(E4, W40, pA0); pA1 = f2fma(E4, W41, pA1);
                pA2 = f2fma(E4, W42, pA2); pA3 = f2fma(E4, W43, pA3);

                u64 F0 = bc2(b0), F1 = bc2(b1), F2 = bc2(b2), F3 = bc2(b3), F4 = bc2(b4);
                u64 pB0 = f2fma(F0, W00, 0ull), pB1 = f2fma(F0, W01, 0ull);
                u64 pB2 = f2fma(F0, W02, 0ull), pB3 = f2fma(F0, W03, 0ull);
                pB0 = f2fma(F1, W10, pB0); pB1 = f2fma(F1, W11, pB1);
                pB2 = f2fma(F1, W12, pB2); pB3 = f2fma(F1, W13, pB3);
                pB0 = f2fma(F2, W20, pB0); pB1 = f2fma(F2, W21, pB1);
                pB2 = f2fma(F2, W22, pB2); pB3 = f2fma(F2, W23, pB3);
                pB0 = f2fma(F3, W30, pB0); pB1 = f2fma(F3, W31, pB1);
                pB2 = f2fma(F3, W32, pB2); pB3 = f2fma(F3, W33, pB3);
                pB0 = f2fma(F4, W40, pB0); pB1 = f2fma(F4, W41, pB1);
                pB2 = f2fma(F4, W42, pB2); pB3 = f2fma(F4, W43, pB3);

                float q0, q1, q2, q3, q4, q5, q6, q7;
                float u, pA = 0.f, pB = 0.f;
                up2(pA0, q0, q1); up2(pA1, q2, q3); up2(pA2, q4, q5); up2(pA3, q6, q7);
                u = xl0.x + xa0.x + q0; pA = fmaf(at0.x, fmaxf(u, 0.f) + 0.2f * fminf(u, 0.f), pA);
                u = xl0.y + xa0.y + q1; pA = fmaf(at0.y, fmaxf(u, 0.f) + 0.2f * fminf(u, 0.f), pA);
                u = xl0.z + xa0.z + q2; pA = fmaf(at0.z, fmaxf(u, 0.f) + 0.2f * fminf(u, 0.f), pA);
                u = xl0.w + xa0.w + q3; pA = fmaf(at0.w, fmaxf(u, 0.f) + 0.2f * fminf(u, 0.f), pA);
                u = xl1.x + xa1.x + q4; pA = fmaf(at1.x, fmaxf(u, 0.f) + 0.2f * fminf(u, 0.f), pA);
                u = xl1.y + xa1.y + q5; pA = fmaf(at1.y, fmaxf(u, 0.f) + 0.2f * fminf(u, 0.f), pA);
                u = xl1.z + xa1.z + q6; pA = fmaf(at1.z, fmaxf(u, 0.f) + 0.2f * fminf(u, 0.f), pA);
                u = xl1.w + xa1.w + q7; pA = fmaf(at1.w, fmaxf(u, 0.f) + 0.2f * fminf(u, 0.f), pA);
                up2(pB0, q0, q1); up2(pB1, q2, q3); up2(pB2, q4, q5); up2(pB3, q6, q7);
                u = xl0.x + xb0.x + q0; pB = fmaf(at0.x, fmaxf(u, 0.f) + 0.2f * fminf(u, 0.f), pB);
                u = xl0.y + xb0.y + q1; pB = fmaf(at0.y, fmaxf(u, 0.f) + 0.2f * fminf(u, 0.f), pB);
                u = xl0.z + xb0.z + q2; pB = fmaf(at0.z, fmaxf(u, 0.f) + 0.2f * fminf(u, 0.f), pB);
                u = xl0.w + xb0.w + q3; pB = fmaf(at0.w, fmaxf(u, 0.f) + 0.2f * fminf(u, 0.f), pB);
                u = xl1.x + xb1.x + q4; pB = fmaf(at1.x, fmaxf(u, 0.f) + 0.2f * fminf(u, 0.f), pB);
                u = xl1.y + xb1.y + q5; pB = fmaf(at1.y, fmaxf(u, 0.f) + 0.2f * fminf(u, 0.f), pB);
                u = xl1.z + xb1.z + q6; pB = fmaf(at1.z, fmaxf(u, 0.f) + 0.2f * fminf(u, 0.f), pB);
                u = xl1.w + xb1.w + q7; pB = fmaf(at1.w, fmaxf(u, 0.f) + 0.2f * fminf(u, 0.f), pB);

                pA += __shfl_xor_sync(0xffffffffu, pA, 1);
                pB += __shfl_xor_sync(0xffffffffu, pB, 1);
                pA += __shfl_xor_sync(0xffffffffu, pA, 2);
                pB += __shfl_xor_sync(0xffffffffu, pB, 2);
                pA += __shfl_xor_sync(0xffffffffu, pA, 4);
                pB += __shfl_xor_sync(0xffffffffu, pB, 4);

                float wA;
                if (pA <= mA) {
                    wA = __expf(pA - mA);
                } else {
                    float fac = __expf(mA - pA);
                    swA *= fac;
                    accA0 = scale4(accA0, fac); accA1 = scale4(accA1, fac);
                    mA = pA;
                    wA = 1.f;
                }
                swA += wA;
                accA0 = fma4(wA, xl0, accA0);
                accA1 = fma4(wA, xl1, accA1);

                float wB;
                if (pB <= mB) {
                    wB = __expf(pB - mB);
                } else {
                    float fac = __expf(mB - pB);
                    swB *= fac;
                    accB0 = scale4(accB0, fac); accB1 = scale4(accB1, fac);
                    mB = pB;
                    wB = 1.f;
                }
                swB += wB;
                accB0 = fma4(wB, xl0, accB0);
                accB1 = fma4(wB, xl1, accB1);

                a0 = na0; a1 = na1; a2 = na2; a3 = na3; a4 = na4;
                b0 = nb0; b1 = nb1; b2 = nb2; b3 = nb3; b4 = nb4;
                eroA = nA; eroB = nB;
                xlp += RS;
            }
            __syncthreads();
        }

        if (dl < 58) {
            float4 bi0 = ld4(BI + j0), bi1 = ld4(BI + j0 + 4);
            float invA = 1.f / (swA + 1e-16f);
            float invB = 1.f / (swB + 1e-16f);
            float* hA = H + d0 * RS + j0;
            float* hB = H + d1 * RS + j0;
            st4(hA,     relu4(add4(scale4(accA0, invA), bi0)));
            st4(hA + 4, relu4(add4(scale4(accA1, invA), bi1)));
            st4(hB,     relu4(add4(scale4(accB0, invB), bi0)));
            st4(hB + 4, relu4(add4(scale4(accB1, invB), bi1)));
        }
        __syncthreads();
    }

    // ---------------- Phase C: pool1 -> t[n] ----------------
    float* TS = XR;   // 116 floats
    for (int i = tid; i < HID * HID; i += GTHR) W1s[i] = pW1[i];
    if (tid < HID) { BV[tid] = pb1[tid]; ATT[tid] = pw2[tid]; }
    __syncthreads();
    {
        float4 w20 = ld4(ATT + j0), w21 = ld4(ATT + j0 + 4);
        #pragma unroll 1
        for (int which = 0; which < 2; which++) {
            int d = which ? d1 : d0;
            float4 a0 = ld4(BV + j0), a1 = ld4(BV + j0 + 4);
            const float* hr = H + d * RS;
            #pragma unroll 4
            for (int c = 0; c < HID; c++) {
                float xv = hr[c];
                const float* wr = W1s + c * HID + j0;
                a0 = fma4(xv, ld4(wr), a0);
                a1 = fma4(xv, ld4(wr + 4), a1);
            }
            float part = 0.f;
            part = fmaf(tanhf(a0.x), w20.x, part);
            part = fmaf(tanhf(a0.y), w20.y, part);
            part = fmaf(tanhf(a0.z), w20.z, part);
            part = fmaf(tanhf(a0.w), w20.w, part);
            part = fmaf(tanhf(a1.x), w21.x, part);
            part = fmaf(tanhf(a1.y), w21.y, part);
            part = fmaf(tanhf(a1.z), w21.z, part);
            part = fmaf(tanhf(a1.w), w21.w, part);
            part += __shfl_xor_sync(0xffffffffu, part, 1);
            part += __shfl_xor_sync(0xffffffffu, part, 2);
            part += __shfl_xor_sync(0xffffffffu, part, 4);
            if (dl < 58 && jg == 0) { TS[d] = part; g_t[g * NROI + d] = part; }
        }
    }
    gridbar(&g_bar2, &g_rel2, &g_done2);

    // ---------------- Phase D: global softmax + head ----------------
    float* red = ES;   // 512 floats
    {
        float mx = -3.0e38f;
        for (int i = tid; i < NNODE; i += GTHR) mx = fmaxf(mx, g_t[i]);
        red[tid] = mx;
        __syncthreads();
        for (int o = 256; o > 0; o >>= 1) {
            if (tid < o) red[tid] = fmaxf(red[tid], red[tid + o]);
            __syncthreads();
        }
        float M = red[0];
        __syncthreads();
        float s = 0.f;
        for (int i = tid; i < NNODE; i += GTHR) s += __expf(g_t[i] - M);
        red[tid] = s;
        __syncthreads();
        for (int o = 256; o > 0; o >>= 1) {
            if (tid < o) red[tid] += red[tid + o];
            __syncthreads();
        }
        float invS = 1.f / red[0];
        __syncthreads();

        float* wex    = XL;        // 116
        float* pooled = BEs;       // 64
        float* y      = XL + 200;  // 116
        if (tid < NROI) wex[tid] = __expf(TS[tid] - M) * invS;
        __syncthreads();
        if (tid < HID) {
            float s2 = 0.f;
            for (int n = 0; n < NROI; n++) s2 = fmaf(H[n * RS + tid], wex[n], s2);
            pooled[tid] = s2;
        }
        __syncthreads();
        if (tid < NROI) {
            float a = __ldg(l1b + tid);
            for (int c = 0; c < HID; c++) a = fmaf(pooled[c], __ldg(l1W + c * INCH + tid), a);
            y[tid] = fmaxf(a, 0.f);
        }
        __syncthreads();
        if (tid < 2) {
            float o = __ldg(l2b + tid);
            for (int j = 0; j < NROI; j++) o = fmaf(y[j], __ldg(l2W + j * 2 + tid), o);
            out[g * 2 + tid] = o;
        }
    }
}

extern "C" void kernel_launch(void* const* d_in, const int* in_sizes, int n_in,
                              void* d_out, int out_size)
{
    const float* x    = (const float*)d_in[0];
    const float* ea   = (const float*)d_in[1];
    const float* emb  = (const float*)d_in[2];
    const float* encW = (const float*)d_in[3];
    const float* encb = (const float*)d_in[4];
    const float* bng  = (const float*)d_in[5];
    const float* bnb  = (const float*)d_in[6];
    const float* gWe  = (const float*)d_in[7];
    const float* gbe  = (const float*)d_in[8];
    const float* gW1  = (const float*)d_in[9];
    const float* gb1  = (const float*)d_in[10];
    const float* gW2  = (const float*)d_in[11];
    const float* gb2  = (const float*)d_in[12];
    const float* aWl  = (const float*)d_in[13];
    const float* abl  = (const float*)d_in[14];
    const float* aWr  = (const float*)d_in[15];
    const float* abr  = (const float*)d_in[16];
    const float* aat  = (const float*)d_in[17];
    const float* aWe  = (const float*)d_in[18];
    const float* abi  = (const float*)d_in[19];
    const float* pW1  = (const float*)d_in[20];
    const float* pb1  = (const float*)d_in[21];
    const float* pw2  = (const float*)d_in[22];
    const float* l1W  = (const float*)d_in[23];
    const float* l1b  = (const float*)d_in[24];
    const float* l2W  = (const float*)d_in[25];
    const float* l2b  = (const float*)d_in[26];
    const int*   gid  = (const int*)d_in[29];
    float* out = (float*)d_out;

    const int smMega = (3 * NROI * RS + 2 * HID * HID + EDIM * HID + ESF + 6 * HID) * 4;
    cudaFuncSetAttribute(k_mega, cudaFuncAttributeMaxDynamicSharedMemorySize, smMega);

    k_mega<<<NGR, GTHR, smMega>>>(x, ea, emb, gid, encW, encb, bng, bnb,
                                  gWe, gbe, gW1, gb1, gW2, gb2,
                                  aWl, abl, aWr, abr, aat, aWe, abi,
                                  pW1, pb1, pw2, l1W, l1b, l2W, l2b, out);
}